// round 12
// baseline (speedup 1.0000x reference)
#include <cuda_runtime.h>
#include <cuda_bf16.h>
#include <math.h>
#include <stdint.h>

// ---------------- problem constants ----------------
#define Bn   2
#define Sn   2048
#define Dn   1024
#define Hn   8
#define HDn  128
#define Vn   32000
#define Ln   6
#define Mtok (Bn*Sn)      // 4096
#define FFn  (4*Dn)       // 4096
#define SCALE_ 0.08838834764831845f   // 128^-0.5

// ---------------- scratch (device globals; no cudaMalloc allowed) ----------------
__device__ float g_h  [(size_t)Mtok*Dn];
__device__ float g_ln [(size_t)Mtok*Dn];
__device__ float g_qkv[(size_t)3*Mtok*Dn];
__device__ float g_ao [(size_t)Mtok*Dn];
__device__ float g_mid[(size_t)Mtok*FFn];
__device__ uint32_t g_qh2[(size_t)Bn*Hn*Sn*64];
__device__ uint32_t g_ql2[(size_t)Bn*Hn*Sn*64];
__device__ uint32_t g_kh2[(size_t)Bn*Hn*Sn*64];
__device__ uint32_t g_kl2[(size_t)Bn*Hn*Sn*64];
__device__ uint32_t g_vh2T[(size_t)Bn*Hn*HDn*(Sn/2)];
__device__ uint32_t g_vl2T[(size_t)Bn*Hn*HDn*(Sn/2)];
__device__ float g_biasn[Hn*Sn];
// tf32-pre-rounded weights ([K][N], same layout as inputs)
#define OFF_WQKV ((size_t)0)
#define OFF_WO   (OFF_WQKV + (size_t)Ln*3*Dn*Dn)
#define OFF_W1   (OFF_WO   + (size_t)Ln*Dn*Dn)
#define OFF_W2   (OFF_W1   + (size_t)Ln*Dn*FFn)
#define OFF_WHEAD (OFF_W2  + (size_t)Ln*FFn*Dn)
#define NW_TOTAL (OFF_WHEAD + (size_t)Dn*Vn)
__device__ float g_w[NW_TOTAL];

// ---------------- helpers ----------------
__device__ __forceinline__ uint32_t f2tf32(float f) {
    uint32_t u;
    asm("cvt.rna.tf32.f32 %0, %1;" : "=r"(u) : "f"(f));
    return u;
}
__device__ __forceinline__ float tfv(float f) { return __uint_as_float(f2tf32(f)); }

__device__ __forceinline__ void cp16(void* dst_smem, const void* src) {
    uint32_t d = (uint32_t)__cvta_generic_to_shared(dst_smem);
    asm volatile("cp.async.cg.shared.global [%0], [%1], 16;" :: "r"(d), "l"(src));
}
#define CP_COMMIT asm volatile("cp.async.commit_group;" ::: "memory")

// split f0,f1 into bf16 hi/lo pairs packed as b32 (low half = first element)
__device__ __forceinline__ void cvt_pair(float f0, float f1, uint32_t& hi, uint32_t& lo) {
    __nv_bfloat16 h0 = __float2bfloat16(f0);
    __nv_bfloat16 h1 = __float2bfloat16(f1);
    __nv_bfloat16 l0 = __float2bfloat16(f0 - __bfloat162float(h0));
    __nv_bfloat16 l1 = __float2bfloat16(f1 - __bfloat162float(h1));
    hi = ((uint32_t)__bfloat16_as_ushort(h1) << 16) | (uint32_t)__bfloat16_as_ushort(h0);
    lo = ((uint32_t)__bfloat16_as_ushort(l1) << 16) | (uint32_t)__bfloat16_as_ushort(l0);
}

#define MMA_BF16(C, A0,A1,A2,A3, B0,B1) \
    asm volatile("mma.sync.aligned.m16n8k16.row.col.f32.bf16.bf16.f32 " \
        "{%0,%1,%2,%3}, {%4,%5,%6,%7}, {%8,%9}, {%0,%1,%2,%3};" \
        : "+f"((C)[0]), "+f"((C)[1]), "+f"((C)[2]), "+f"((C)[3]) \
        : "r"(A0), "r"(A1), "r"(A2), "r"(A3), "r"(B0), "r"(B1))

#define MMA_TF32(C, A0,A1,A2,A3, B0,B1) \
    asm volatile("mma.sync.aligned.m16n8k8.row.col.f32.tf32.tf32.f32 " \
        "{%0,%1,%2,%3}, {%4,%5,%6,%7}, {%8,%9}, {%0,%1,%2,%3};" \
        : "+f"((C)[0]), "+f"((C)[1]), "+f"((C)[2]), "+f"((C)[3]) \
        : "r"(A0), "r"(A1), "r"(A2), "r"(A3), "r"(B0), "r"(B1))

__device__ __forceinline__ float blockReduceSum(float v, float* sm) {
    int lane = threadIdx.x & 31, wid = threadIdx.x >> 5;
    #pragma unroll
    for (int o = 16; o > 0; o >>= 1) v += __shfl_xor_sync(0xffffffffu, v, o);
    if (lane == 0) sm[wid] = v;
    __syncthreads();
    if (threadIdx.x < 32) {
        float t = (threadIdx.x < 8) ? sm[threadIdx.x] : 0.f;
        #pragma unroll
        for (int o = 4; o > 0; o >>= 1) t += __shfl_xor_sync(0xffffffffu, t, o);
        if (threadIdx.x == 0) sm[0] = t;
    }
    __syncthreads();
    float r = sm[0];
    __syncthreads();
    return r;
}

// ---------------- weight tf32 pre-round ----------------
__global__ __launch_bounds__(256)
void cvtw_kernel(const float4* __restrict__ src, float4* __restrict__ dst, int n4) {
    int i = blockIdx.x * 256 + threadIdx.x;
    if (i < n4) {
        float4 v = src[i];
        dst[i] = make_float4(tfv(v.x), tfv(v.y), tfv(v.z), tfv(v.w));
    }
}

// ---------------- embedding gather ----------------
__global__ void embed_kernel(const int* __restrict__ x,
                             const float* __restrict__ emb,
                             float* __restrict__ h) {
    int t = blockIdx.x;
    int tok = x[t];
    ((float4*)(h + (size_t)t*Dn))[threadIdx.x] =
        ((const float4*)(emb + (size_t)tok*Dn))[threadIdx.x];
}

// ---------------- LayerNorm (optionally fused double LN); output tf32-rounded ----------------
__global__ __launch_bounds__(256)
void ln_kernel(const float* __restrict__ x,
               const float* __restrict__ g,  const float* __restrict__ b,
               const float* __restrict__ g2, const float* __restrict__ b2,
               float* __restrict__ y, int dbl) {
    __shared__ float sm[32];
    int row = blockIdx.x;
    float4 v = ((const float4*)(x + (size_t)row*Dn))[threadIdx.x];
    float s  = v.x + v.y + v.z + v.w;
    float ss = v.x*v.x + v.y*v.y + v.z*v.z + v.w*v.w;
    float sum   = blockReduceSum(s, sm);
    float sumsq = blockReduceSum(ss, sm);
    float mean = sum * (1.f/Dn);
    float var  = sumsq * (1.f/Dn) - mean*mean;
    float r = rsqrtf(var + 1e-5f);
    int c = threadIdx.x * 4;
    float4 gv = *(const float4*)(g + c);
    float4 bv = *(const float4*)(b + c);
    float4 o;
    o.x = (v.x - mean)*r*gv.x + bv.x;
    o.y = (v.y - mean)*r*gv.y + bv.y;
    o.z = (v.z - mean)*r*gv.z + bv.z;
    o.w = (v.w - mean)*r*gv.w + bv.w;
    if (dbl) {
        s  = o.x + o.y + o.z + o.w;
        ss = o.x*o.x + o.y*o.y + o.z*o.z + o.w*o.w;
        sum   = blockReduceSum(s, sm);
        sumsq = blockReduceSum(ss, sm);
        mean = sum * (1.f/Dn);
        var  = sumsq * (1.f/Dn) - mean*mean;
        r = rsqrtf(var + 1e-5f);
        float4 g2v = *(const float4*)(g2 + c);
        float4 b2v = *(const float4*)(b2 + c);
        o.x = (o.x - mean)*r*g2v.x + b2v.x;
        o.y = (o.y - mean)*r*g2v.y + b2v.y;
        o.z = (o.z - mean)*r*g2v.z + b2v.z;
        o.w = (o.w - mean)*r*g2v.w + b2v.w;
    }
    o.x = tfv(o.x); o.y = tfv(o.y); o.z = tfv(o.z); o.w = tfv(o.w);
    ((float4*)(y + (size_t)row*Dn))[threadIdx.x] = o;
}

// ---------------- TF32 tensor-core GEMM, cp.async 4-stage pipeline (frozen) ----------------
#define TBM 128
#define TBN 128
#define SA_PITCH 20
#define SB_PITCH 136
#define STG_A (128*SA_PITCH)
#define STG_B (16*SB_PITCH)
#define STG   (STG_A + STG_B)
#define TG_SMEM (4*STG*4)

__global__ __launch_bounds__(256, 2)
void tgemm_kernel(const float* __restrict__ A, const float* __restrict__ B,
                  const float* __restrict__ bias, const float* __restrict__ add,
                  float* __restrict__ C, int M, int N, int K,
                  int relu, int round_out, int swapxy,
                  size_t zB, size_t zBias, size_t zC) {
    extern __shared__ float smf[];

    B += (size_t)blockIdx.z * zB;
    if (bias) bias += (size_t)blockIdx.z * zBias;
    C += (size_t)blockIdx.z * zC;

    int tid  = threadIdx.x;
    int bxm = swapxy ? blockIdx.x : blockIdx.y;
    int bxn = swapxy ? blockIdx.y : blockIdx.x;
    int brow = bxm * TBM;
    int bcol = bxn * TBN;

    int warp = tid >> 5, lane = tid & 31;
    int gid = lane >> 2, tig = lane & 3;
    int warpM = (warp >> 2) * 64;
    int warpN = (warp & 3) * 32;

    const float* Ag = A + (size_t)brow * K;
    const float* Bg = B + bcol;

    int am0 = tid >> 1,          ak0 = (tid & 1) << 3;
    int bk0 = tid >> 5,          bn0 = (tid & 31) << 2;
    int bk1 = bk0 + 8;

    int nslab = K >> 4;
    auto issue = [&](int s) {
        float* As_ = smf + (s & 3) * STG;
        float* Bs_ = As_ + STG_A;
        int k0 = s << 4;
        const float* ag = Ag + (size_t)am0*K + k0 + ak0;
        cp16(As_ + am0*SA_PITCH + ak0,     ag);
        cp16(As_ + am0*SA_PITCH + ak0 + 4, ag + 4);
        cp16(Bs_ + bk0*SB_PITCH + bn0, Bg + (size_t)(k0+bk0)*N + bn0);
        cp16(Bs_ + bk1*SB_PITCH + bn0, Bg + (size_t)(k0+bk1)*N + bn0);
    };

    issue(0); CP_COMMIT;
    issue(1); CP_COMMIT;
    issue(2); CP_COMMIT;

    float acc[4][4][4] = {};

    for (int i = 0; i < nslab; i++) {
        asm volatile("cp.async.wait_group 2;" ::: "memory");
        __syncthreads();
        const float* As_ = smf + (i & 3) * STG;
        const float* Bs_ = As_ + STG_A;
        #pragma unroll
        for (int ks = 0; ks < 2; ks++) {
            int kb = ks * 8;
            uint32_t af[4][4], bf[4][2];
            #pragma unroll
            for (int mt = 0; mt < 4; mt++) {
                int r = warpM + mt*16 + gid;
                af[mt][0] = __float_as_uint(As_[(size_t)r    *SA_PITCH + kb + tig    ]);
                af[mt][1] = __float_as_uint(As_[(size_t)(r+8)*SA_PITCH + kb + tig    ]);
                af[mt][2] = __float_as_uint(As_[(size_t)r    *SA_PITCH + kb + tig + 4]);
                af[mt][3] = __float_as_uint(As_[(size_t)(r+8)*SA_PITCH + kb + tig + 4]);
            }
            #pragma unroll
            for (int nt = 0; nt < 4; nt++) {
                int c = warpN + nt*8 + gid;
                bf[nt][0] = __float_as_uint(Bs_[(size_t)(kb+tig  )*SB_PITCH + c]);
                bf[nt][1] = __float_as_uint(Bs_[(size_t)(kb+tig+4)*SB_PITCH + c]);
            }
            #pragma unroll
            for (int mt = 0; mt < 4; mt++)
                #pragma unroll
                for (int nt = 0; nt < 4; nt++)
                    MMA_TF32(acc[mt][nt], af[mt][0], af[mt][1], af[mt][2], af[mt][3],
                             bf[nt][0], bf[nt][1]);
        }
        if (i + 3 < nslab) issue(i + 3);
        CP_COMMIT;
    }

    #pragma unroll
    for (int mt = 0; mt < 4; mt++) {
        int r0 = brow + warpM + mt*16 + gid;
        int r1 = r0 + 8;
        #pragma unroll
        for (int nt = 0; nt < 4; nt++) {
            int c = bcol + warpN + nt*8 + tig*2;
            float v00 = acc[mt][nt][0], v01 = acc[mt][nt][1];
            float v10 = acc[mt][nt][2], v11 = acc[mt][nt][3];
            if (bias) {
                float bb0 = bias[c], bb1 = bias[c+1];
                v00 += bb0; v01 += bb1; v10 += bb0; v11 += bb1;
            }
            if (relu) {
                v00 = fmaxf(v00, 0.f); v01 = fmaxf(v01, 0.f);
                v10 = fmaxf(v10, 0.f); v11 = fmaxf(v11, 0.f);
            }
            if (round_out) {
                v00 = tfv(v00); v01 = tfv(v01);
                v10 = tfv(v10); v11 = tfv(v11);
            }
            if (add) {
                const float* ad0 = add + (size_t)r0*N + c;
                const float* ad1 = add + (size_t)r1*N + c;
                v00 += ad0[0]; v01 += ad0[1];
                v10 += ad1[0]; v11 += ad1[1];
            }
            *(float2*)(C + (size_t)r0*N + c) = make_float2(v00, v01);
            *(float2*)(C + (size_t)r1*N + c) = make_float2(v10, v11);
        }
    }
}

// ---------------- rel-pos bias table (layer-invariant) ----------------
__global__ void bias_init_kernel(const float* __restrict__ rel,
                                 float* __restrict__ biasn) {
    int n = blockIdx.x * 256 + threadIdx.x;
    if (n >= Sn) return;
    float inv_log8 = 1.0f / logf(8.0f);
    int bucket;
    if (n < 16) bucket = n;
    else {
        int vb = 16 + (int)((logf((float)n * (1.0f/16.0f)) * inv_log8) * 16.0f);
        bucket = vb < 31 ? vb : 31;
    }
    for (int h = 0; h < Hn; h++)
        biasn[h*Sn + n] = rel[bucket*Hn + h] * SCALE_;
}

// ---------------- merged attention-operand conversion (Q/K pack + V transpose) ----------------
// blocks [0, Mtok): Q/K bf16 hi/lo pack; blocks [Mtok, Mtok+512): V transpose pack.
__global__ __launch_bounds__(256)
void cvt_attn_kernel(const float* __restrict__ q, const float* __restrict__ k,
                     const float* __restrict__ v,
                     uint32_t* __restrict__ qh2, uint32_t* __restrict__ ql2,
                     uint32_t* __restrict__ kh2, uint32_t* __restrict__ kl2,
                     uint32_t* __restrict__ vh2T, uint32_t* __restrict__ vl2T) {
    __shared__ float vs[64][129];
    int bx = blockIdx.x;
    if (bx < Mtok) {
        int tok = bx;
        int b = tok >> 11, s = tok & 2047;
        const float2* qr = (const float2*)(q + (size_t)tok*Dn);
        const float2* kr = (const float2*)(k + (size_t)tok*Dn);
        for (int p = threadIdx.x; p < 512; p += 256) {
            int h = p >> 6, hdp = p & 63;
            size_t o = ((size_t)(b*Hn + h)*Sn + s)*64 + hdp;
            float2 vv = qr[p];
            uint32_t hi, lo;
            cvt_pair(vv.x, vv.y, hi, lo);
            qh2[o] = hi; ql2[o] = lo;
            vv = kr[p];
            cvt_pair(vv.x, vv.y, hi, lo);
            kh2[o] = hi; kl2[o] = lo;
        }
    } else {
        int idx = bx - Mtok;            // 0..511
        int kv0 = (idx & 31) * 64;
        int bh = idx >> 5, b = bh >> 3, h = bh & 7;
        const float* vb = v + ((size_t)b*Sn + kv0)*Dn + h*HDn;
        for (int i2 = threadIdx.x; i2 < 64*32; i2 += 256) {
            int r = i2 >> 5, c4 = (i2 & 31) << 2;
            float4 t = *(const float4*)(vb + (size_t)r*Dn + c4);
            vs[r][c4] = t.x; vs[r][c4+1] = t.y; vs[r][c4+2] = t.z; vs[r][c4+3] = t.w;
        }
        __syncthreads();
        int hd  = threadIdx.x >> 1;
        int kp0 = (threadIdx.x & 1) * 16;
        uint32_t* oh = vh2T + ((size_t)bh*HDn + hd)*(Sn/2) + (kv0 >> 1) + kp0;
        uint32_t* ol = vl2T + ((size_t)bh*HDn + hd)*(Sn/2) + (kv0 >> 1) + kp0;
        for (int kp = 0; kp < 16; kp++) {
            float f0 = vs[2*(kp0+kp)  ][hd];
            float f1 = vs[2*(kp0+kp)+1][hd];
            uint32_t hi, lo;
            cvt_pair(f0, f1, hi, lo);
            oh[kp] = hi; ol[kp] = lo;
        }
    }
}

// ---------------- fused flash attention ----------------
#define FQP 68
#define FVP 36
#define FSM_U32 (4*64*FQP + 2*128*FVP)
#define FLASH_SMEM ((FSM_U32 + 512) * 4)

__global__ __launch_bounds__(256)
void flash_kernel(const uint32_t* __restrict__ qh2, const uint32_t* __restrict__ ql2,
                  const uint32_t* __restrict__ kh2, const uint32_t* __restrict__ kl2,
                  const uint32_t* __restrict__ vh2T, const uint32_t* __restrict__ vl2T,
                  const float* __restrict__ biasn, float* __restrict__ out) {
    extern __shared__ uint32_t smu[];
    uint32_t* qh  = smu;
    uint32_t* ql  = smu + 64*FQP;
    uint32_t* khb = smu + 2*64*FQP;
    uint32_t* klb = smu + 3*64*FQP;
    uint32_t* vhb = smu + 4*64*FQP;
    uint32_t* vlb = vhb + 128*FVP;
    float* m_s    = (float*)(vlb + 128*FVP);
    float* l_s    = m_s + 64;
    float* rmax   = l_s + 64;
    float* rsum   = rmax + 128;
    float* bias_s = rsum + 128;

    int ti = gridDim.x - 1 - (int)blockIdx.x;
    int bh = blockIdx.y, b = bh >> 3, h = bh & 7;
    int tid = threadIdx.x;
    int warp = tid >> 5, lane = tid & 31;
    int g = lane >> 2, t = lane & 3;
    int warpM  = (warp & 3) << 4;
    int grp    = warp >> 2;
    int warpNS = grp << 5;
    int warpNV = grp << 6;

    {
        size_t qoff = ((size_t)bh*Sn + (size_t)ti*64)*64;
        for (int idx = tid; idx < 1024; idx += 256) {
            int r = idx >> 4, c4 = (idx & 15) << 2;
            *(uint4*)&qh[r*FQP + c4] = *(const uint4*)(qh2 + qoff + (size_t)r*64 + c4);
            *(uint4*)&ql[r*FQP + c4] = *(const uint4*)(ql2 + qoff + (size_t)r*64 + c4);
        }
        if (tid < 64) { m_s[tid] = -INFINITY; l_s[tid] = 0.f; }
    }

    float acc[8][4] = {};
    int iloc0 = warpM + g;

    for (int jt = 0; jt <= ti; jt++) {
        __syncthreads();
        size_t koff = ((size_t)bh*Sn + (size_t)jt*64)*64;
        for (int idx = tid; idx < 1024; idx += 256) {
            int r = idx >> 4, c4 = (idx & 15) << 2;
            *(uint4*)&khb[r*FQP + c4] = *(const uint4*)(kh2 + koff + (size_t)r*64 + c4);
            *(uint4*)&klb[r*FQP + c4] = *(const uint4*)(kl2 + koff + (size_t)r*64 + c4);
        }
        size_t voff = (size_t)bh*HDn*(Sn/2) + (size_t)jt*32;
        for (int idx = tid; idx < 1024; idx += 256) {
            int r = idx >> 3, c4 = (idx & 7) << 2;
            *(uint4*)&vhb[r*FVP + c4] = *(const uint4*)(vh2T + voff + (size_t)r*(Sn/2) + c4);
            *(uint4*)&vlb[r*FVP + c4] = *(const uint4*)(vl2T + voff + (size_t)r*(Sn/2) + c4);
        }
        if (tid < 128) {
            int n = (ti - jt)*64 - 63 + tid;
            bias_s[tid] = biasn[h*Sn + (n > 0 ? n : 0)];
        }
        __syncthreads();

        float sacc[4][4] = {};
        #pragma unroll
        for (int ks = 0; ks < 8; ks++) {
            int c0 = 8*ks + t, c1 = c0 + 4;
            int rA = iloc0*FQP;
            uint32_t ah0 = qh[rA + c0],           ah1 = qh[rA + 8*FQP + c0];
            uint32_t ah2 = qh[rA + c1],           ah3 = qh[rA + 8*FQP + c1];
            uint32_t al0 = ql[rA + c0],           al1 = ql[rA + 8*FQP + c0];
            uint32_t al2 = ql[rA + c1],           al3 = ql[rA + 8*FQP + c1];
            #pragma unroll
            for (int nt = 0; nt < 4; nt++) {
                int rB = (warpNS + nt*8 + g)*FQP;
                uint32_t kb0 = khb[rB + c0], kb1 = khb[rB + c1];
                uint32_t kc0 = klb[rB + c0], kc1 = klb[rB + c1];
                MMA_BF16(sacc[nt], ah0, ah1, ah2, ah3, kb0, kb1);
                MMA_BF16(sacc[nt], ah0, ah1, ah2, ah3, kc0, kc1);
                MMA_BF16(sacc[nt], al0, al1, al2, al3, kb0, kb1);
            }
        }

        int i0 = ti*64 + iloc0;
        #pragma unroll
        for (int nt = 0; nt < 4; nt++) {
            int jloc = warpNS + nt*8 + 2*t;
            int j0 = jt*64 + jloc;
            int d00 = iloc0 - jloc + 63;
            sacc[nt][0] = (j0     <= i0    ) ? (sacc[nt][0] + bias_s[d00    ]) * SCALE_ : -INFINITY;
            sacc[nt][1] = (j0 + 1 <= i0    ) ? (sacc[nt][1] + bias_s[d00 - 1]) * SCALE_ : -INFINITY;
            sacc[nt][2] = (j0     <= i0 + 8) ? (sacc[nt][2] + bias_s[d00 + 8]) * SCALE_ : -INFINITY;
            sacc[nt][3] = (j0 + 1 <= i0 + 8) ? (sacc[nt][3] + bias_s[d00 + 7]) * SCALE_ : -INFINITY;
        }

        float mx0 = fmaxf(fmaxf(sacc[0][0], sacc[0][1]), fmaxf(sacc[1][0], sacc[1][1]));
        mx0 = fmaxf(mx0, fmaxf(fmaxf(sacc[2][0], sacc[2][1]), fmaxf(sacc[3][0], sacc[3][1])));
        float mx1 = fmaxf(fmaxf(sacc[0][2], sacc[0][3]), fmaxf(sacc[1][2], sacc[1][3]));
        mx1 = fmaxf(mx1, fmaxf(fmaxf(sacc[2][2], sacc[2][3]), fmaxf(sacc[3][2], sacc[3][3])));
        mx0 = fmaxf(mx0, __shfl_xor_sync(0xffffffffu, mx0, 1));
        mx0 = fmaxf(mx0, __shfl_xor_sync(0xffffffffu, mx0, 2));
        mx1 = fmaxf(mx1, __shfl_xor_sync(0xffffffffu, mx1, 1));
        mx1 = fmaxf(mx1, __shfl_xor_sync(0xffffffffu, mx1, 2));
        if (t == 0) {
            rmax[grp*64 + iloc0]     = mx0;
            rmax[grp*64 + iloc0 + 8] = mx1;
        }
        __syncthreads();

        float mold0 = m_s[iloc0], mold1 = m_s[iloc0 + 8];
        float mnew0 = fmaxf(mold0, fmaxf(rmax[iloc0],     rmax[64 + iloc0]));
        float mnew1 = fmaxf(mold1, fmaxf(rmax[iloc0 + 8], rmax[64 + iloc0 + 8]));
        float fac0 = __expf(mold0 - mnew0);
        float fac1 = __expf(mold1 - mnew1);

        float sum0 = 0.f, sum1 = 0.f;
        #pragma unroll
        for (int nt = 0; nt < 4; nt++) {
            float p00 = __expf(sacc[nt][0] - mnew0);
            float p01 = __expf(sacc[nt][1] - mnew0);
            float p10 = __expf(sacc[nt][2] - mnew1);
            float p11 = __expf(sacc[nt][3] - mnew1);
            sum0 += p00 + p01; sum1 += p10 + p11;
            int cc = (warpNS >> 1) + nt*4 + t;
            uint32_t hi, lo;
            cvt_pair(p00, p01, hi, lo);
            khb[iloc0*FQP + cc] = hi; klb[iloc0*FQP + cc] = lo;
            cvt_pair(p10, p11, hi, lo);
            khb[(iloc0+8)*FQP + cc] = hi; klb[(iloc0+8)*FQP + cc] = lo;
        }
        sum0 += __shfl_xor_sync(0xffffffffu, sum0, 1);
        sum0 += __shfl_xor_sync(0xffffffffu, sum0, 2);
        sum1 += __shfl_xor_sync(0xffffffffu, sum1, 1);
        sum1 += __shfl_xor_sync(0xffffffffu, sum1, 2);
        if (t == 0) {
            rsum[grp*64 + iloc0]     = sum0;
            rsum[grp*64 + iloc0 + 8] = sum1;
        }

        #pragma unroll
        for (int nt = 0; nt < 8; nt++) {
            acc[nt][0] *= fac0; acc[nt][1] *= fac0;
            acc[nt][2] *= fac1; acc[nt][3] *= fac1;
        }
        __syncthreads();

        if (tid < 64) {
            float mo = m_s[tid];
            float mn = fmaxf(mo, fmaxf(rmax[tid], rmax[64 + tid]));
            l_s[tid] = l_s[tid] * __expf(mo - mn) + rsum[tid] + rsum[64 + tid];
            m_s[tid] = mn;
        }

        #pragma unroll
        for (int ks = 0; ks < 4; ks++) {
            int c0 = 8*ks + t, c1 = c0 + 4;
            int rA = iloc0*FQP;
            uint32_t ah0 = khb[rA + c0],           ah1 = khb[rA + 8*FQP + c0];
            uint32_t ah2 = khb[rA + c1],           ah3 = khb[rA + 8*FQP + c1];
            uint32_t al0 = klb[rA + c0],           al1 = klb[rA + 8*FQP + c0];
            uint32_t al2 = klb[rA + c1],           al3 = klb[rA + 8*FQP + c1];
            #pragma unroll
            for (int nt = 0; nt < 8; nt++) {
                int rB = (warpNV + nt*8 + g)*FVP;
                uint32_t vb0 = vhb[rB + c0], vb1 = vhb[rB + c1];
                uint32_t vc0 = vlb[rB + c0], vc1 = vlb[rB + c1];
                MMA_BF16(acc[nt], ah0, ah1, ah2, ah3, vb0, vb1);
                MMA_BF16(acc[nt], ah0, ah1, ah2, ah3, vc0, vc1);
                MMA_BF16(acc[nt], al0, al1, al2, al3, vb0, vb1);
            }
        }
    }

    __syncthreads();
    float inv0 = 1.f / l_s[iloc0];
    float inv1 = 1.f / l_s[iloc0 + 8];
    int i0 = ti*64 + iloc0;
    #pragma unroll
    for (int nt = 0; nt < 8; nt++) {
        int col = warpNV + nt*8 + 2*t;
        float* op0 = out + ((size_t)b*Sn + i0)*Dn + h*HDn + col;
        float* op1 = op0 + 8*(size_t)Dn;
        *(float2*)op0 = make_float2(tfv(acc[nt][0]*inv0), tfv(acc[nt][1]*inv0));
        *(float2*)op1 = make_float2(tfv(acc[nt][2]*inv1), tfv(acc[nt][3]*inv1));
    }
}

// ---------------- orchestration ----------------
extern "C" void kernel_launch(void* const* d_in, const int* in_sizes, int n_in,
                              void* d_out, int out_size) {
    (void)in_sizes; (void)n_in; (void)out_size;
    const int*   x     = (const int*)  d_in[0];
    const float* tok   = (const float*)d_in[1];
    const float* rel   = (const float*)d_in[2];
    const float* ln_g  = (const float*)d_in[3];
    const float* ln_b  = (const float*)d_in[4];
    const float* Wqkv  = (const float*)d_in[5];
    const float* bqkv  = (const float*)d_in[6];
    const float* Wo    = (const float*)d_in[7];
    const float* bo    = (const float*)d_in[8];
    const float* W1    = (const float*)d_in[9];
    const float* b1    = (const float*)d_in[10];
    const float* W2    = (const float*)d_in[11];
    const float* b2    = (const float*)d_in[12];
    const float* lnf_g = (const float*)d_in[13];
    const float* lnf_b = (const float*)d_in[14];
    const float* Whead = (const float*)d_in[15];
    const float* bhead = (const float*)d_in[16];
    float* out = (float*)d_out;

    float *h, *ln, *qkv, *ao, *mid, *biasn, *w;
    uint32_t *qh2, *ql2, *kh2, *kl2, *vh2T, *vl2T;
    cudaGetSymbolAddress((void**)&h,    g_h);
    cudaGetSymbolAddress((void**)&ln,   g_ln);
    cudaGetSymbolAddress((void**)&qkv,  g_qkv);
    cudaGetSymbolAddress((void**)&ao,   g_ao);
    cudaGetSymbolAddress((void**)&mid,  g_mid);
    cudaGetSymbolAddress((void**)&biasn,g_biasn);
    cudaGetSymbolAddress((void**)&w,    g_w);
    cudaGetSymbolAddress((void**)&qh2,  g_qh2);
    cudaGetSymbolAddress((void**)&ql2,  g_ql2);
    cudaGetSymbolAddress((void**)&kh2,  g_kh2);
    cudaGetSymbolAddress((void**)&kl2,  g_kl2);
    cudaGetSymbolAddress((void**)&vh2T, g_vh2T);
    cudaGetSymbolAddress((void**)&vl2T, g_vl2T);

    cudaFuncSetAttribute(flash_kernel, cudaFuncAttributeMaxDynamicSharedMemorySize,
                         FLASH_SMEM);
    cudaFuncSetAttribute(tgemm_kernel, cudaFuncAttributeMaxDynamicSharedMemorySize,
                         TG_SMEM);

    const float* q = qkv;
    const float* k = qkv + (size_t)Mtok*Dn;
    const float* v = qkv + (size_t)2*Mtok*Dn;

    // ---- side stream for weight pre-rounding (overlaps with main chain) ----
    cudaStream_t s2 = 0;
    cudaEvent_t evF = 0, ev1 = 0, ev2 = 0;
    cudaStreamCreateWithFlags(&s2, cudaStreamNonBlocking);
    cudaEventCreateWithFlags(&evF, cudaEventDisableTiming);
    cudaEventCreateWithFlags(&ev1, cudaEventDisableTiming);
    cudaEventCreateWithFlags(&ev2, cudaEventDisableTiming);

    cudaEventRecord(evF, 0);
    cudaStreamWaitEvent(s2, evF, 0);
    {
        int n4 = (int)(((size_t)Ln*3*Dn*Dn) >> 2);
        cvtw_kernel<<<(n4 + 255)/256, 256, 0, s2>>>((const float4*)Wqkv,
                                                    (float4*)(w + OFF_WQKV), n4);
        cudaEventRecord(ev1, s2);
        n4 = (int)(((size_t)Ln*Dn*Dn) >> 2);
        cvtw_kernel<<<(n4 + 255)/256, 256, 0, s2>>>((const float4*)Wo,
                                                    (float4*)(w + OFF_WO), n4);
        n4 = (int)(((size_t)Ln*Dn*FFn) >> 2);
        cvtw_kernel<<<(n4 + 255)/256, 256, 0, s2>>>((const float4*)W1,
                                                    (float4*)(w + OFF_W1), n4);
        n4 = (int)(((size_t)Ln*FFn*Dn) >> 2);
        cvtw_kernel<<<(n4 + 255)/256, 256, 0, s2>>>((const float4*)W2,
                                                    (float4*)(w + OFF_W2), n4);
        n4 = (int)(((size_t)Dn*Vn) >> 2);
        cvtw_kernel<<<(n4 + 255)/256, 256, 0, s2>>>((const float4*)Whead,
                                                    (float4*)(w + OFF_WHEAD), n4);
        cudaEventRecord(ev2, s2);
    }

    embed_kernel<<<Mtok, 256>>>(x, tok, h);
    bias_init_kernel<<<Sn/256, 256>>>(rel, biasn);

    dim3 gDD(Dn/TBN,  Mtok/TBM);
    dim3 gQKV(Dn/TBN, Mtok/TBM, 3);
    dim3 gDF(FFn/TBN, Mtok/TBM);
    dim3 gDV(Mtok/TBM, Vn/TBN);           // M-fastest for the huge-N head GEMM

    for (int l = 0; l < Ln; l++) {
        ln_kernel<<<Mtok, 256>>>(h, ln_g + (size_t)(l*3+0)*Dn, ln_b + (size_t)(l*3+0)*Dn,
                                 nullptr, nullptr, ln, 0);
        if (l == 0) cudaStreamWaitEvent(0, ev1, 0);
        tgemm_kernel<<<gQKV, 256, TG_SMEM>>>(ln, w + OFF_WQKV + (size_t)l*3*Dn*Dn,
                                    bqkv + (size_t)l*3*Dn, nullptr, qkv,
                                    Mtok, Dn, Dn, 0, 0, 0,
                                    (size_t)Dn*Dn, (size_t)Dn, (size_t)Mtok*Dn);
        cvt_attn_kernel<<<Mtok + (Sn/64)*Bn*Hn, 256>>>(q, k, v,
                                    qh2, ql2, kh2, kl2, vh2T, vl2T);
        flash_kernel<<<dim3(Sn/64, Bn*Hn), 256, FLASH_SMEM>>>(
            qh2, ql2, kh2, kl2, vh2T, vl2T, biasn, ao);
        if (l == 0) cudaStreamWaitEvent(0, ev2, 0);
        tgemm_kernel<<<gDD, 256, TG_SMEM>>>(ao, w + OFF_WO + (size_t)l*Dn*Dn,
                                   bo + (size_t)l*Dn, h, h,
                                   Mtok, Dn, Dn, 0, 0, 0, 0, 0, 0);
        ln_kernel<<<Mtok, 256>>>(h, ln_g + (size_t)(l*3+1)*Dn, ln_b + (size_t)(l*3+1)*Dn,
                                 ln_g + (size_t)(l*3+2)*Dn, ln_b + (size_t)(l*3+2)*Dn, ln, 1);
        tgemm_kernel<<<gDF, 256, TG_SMEM>>>(ln, w + OFF_W1 + (size_t)l*Dn*FFn,
                                   b1 + (size_t)l*FFn, nullptr, mid,
                                   Mtok, FFn, Dn, 1, 1, 0, 0, 0, 0);
        tgemm_kernel<<<gDD, 256, TG_SMEM>>>(mid, w + OFF_W2 + (size_t)l*FFn*Dn,
                                   b2 + (size_t)l*Dn, h, h,
                                   Mtok, Dn, FFn, 0, 0, 0, 0, 0, 0);
    }

    ln_kernel<<<Mtok, 256>>>(h, lnf_g, lnf_b, nullptr, nullptr, ln, 0);
    tgemm_kernel<<<gDV, 256, TG_SMEM>>>(ln, w + OFF_WHEAD, bhead, nullptr, out,
                               Mtok, Vn, Dn, 0, 0, 1, 0, 0, 0);
}

// round 13
// speedup vs baseline: 1.0010x; 1.0010x over previous
#include <cuda_runtime.h>
#include <cuda_bf16.h>
#include <math.h>
#include <stdint.h>

// ---------------- problem constants ----------------
#define Bn   2
#define Sn   2048
#define Dn   1024
#define Hn   8
#define HDn  128
#define Vn   32000
#define Ln   6
#define Mtok (Bn*Sn)      // 4096
#define FFn  (4*Dn)       // 4096
#define SCALE_ 0.08838834764831845f   // 128^-0.5

// ---------------- scratch (device globals; no cudaMalloc allowed) ----------------
__device__ float g_h  [(size_t)Mtok*Dn];
__device__ float g_ln [(size_t)Mtok*Dn];
__device__ float g_qkv[(size_t)3*Mtok*Dn];
__device__ float g_ao [(size_t)Mtok*Dn];
__device__ float g_mid[(size_t)Mtok*FFn];
__device__ uint32_t g_qh2[(size_t)Bn*Hn*Sn*64];
__device__ uint32_t g_ql2[(size_t)Bn*Hn*Sn*64];
__device__ uint32_t g_kh2[(size_t)Bn*Hn*Sn*64];
__device__ uint32_t g_kl2[(size_t)Bn*Hn*Sn*64];
__device__ uint32_t g_vh2T[(size_t)Bn*Hn*HDn*(Sn/2)];
__device__ uint32_t g_vl2T[(size_t)Bn*Hn*HDn*(Sn/2)];
__device__ float g_biasn[Hn*Sn];
// tf32-pre-rounded weights ([K][N], same layout as inputs)
#define OFF_WQKV ((size_t)0)
#define OFF_WO   (OFF_WQKV + (size_t)Ln*3*Dn*Dn)
#define OFF_W1   (OFF_WO   + (size_t)Ln*Dn*Dn)
#define OFF_W2   (OFF_W1   + (size_t)Ln*Dn*FFn)
#define OFF_WHEAD (OFF_W2  + (size_t)Ln*FFn*Dn)
#define NW_TOTAL (OFF_WHEAD + (size_t)Dn*Vn)
__device__ float g_w[NW_TOTAL];

// ---------------- helpers ----------------
__device__ __forceinline__ uint32_t f2tf32(float f) {
    uint32_t u;
    asm("cvt.rna.tf32.f32 %0, %1;" : "=r"(u) : "f"(f));
    return u;
}
__device__ __forceinline__ float tfv(float f) { return __uint_as_float(f2tf32(f)); }

__device__ __forceinline__ void cp16(void* dst_smem, const void* src) {
    uint32_t d = (uint32_t)__cvta_generic_to_shared(dst_smem);
    asm volatile("cp.async.cg.shared.global [%0], [%1], 16;" :: "r"(d), "l"(src));
}
#define CP_COMMIT asm volatile("cp.async.commit_group;" ::: "memory")

// split f0,f1 into bf16 hi/lo pairs packed as b32 (low half = first element)
__device__ __forceinline__ void cvt_pair(float f0, float f1, uint32_t& hi, uint32_t& lo) {
    __nv_bfloat16 h0 = __float2bfloat16(f0);
    __nv_bfloat16 h1 = __float2bfloat16(f1);
    __nv_bfloat16 l0 = __float2bfloat16(f0 - __bfloat162float(h0));
    __nv_bfloat16 l1 = __float2bfloat16(f1 - __bfloat162float(h1));
    hi = ((uint32_t)__bfloat16_as_ushort(h1) << 16) | (uint32_t)__bfloat16_as_ushort(h0);
    lo = ((uint32_t)__bfloat16_as_ushort(l1) << 16) | (uint32_t)__bfloat16_as_ushort(l0);
}

#define MMA_BF16(C, A0,A1,A2,A3, B0,B1) \
    asm volatile("mma.sync.aligned.m16n8k16.row.col.f32.bf16.bf16.f32 " \
        "{%0,%1,%2,%3}, {%4,%5,%6,%7}, {%8,%9}, {%0,%1,%2,%3};" \
        : "+f"((C)[0]), "+f"((C)[1]), "+f"((C)[2]), "+f"((C)[3]) \
        : "r"(A0), "r"(A1), "r"(A2), "r"(A3), "r"(B0), "r"(B1))

#define MMA_TF32(C, A0,A1,A2,A3, B0,B1) \
    asm volatile("mma.sync.aligned.m16n8k8.row.col.f32.tf32.tf32.f32 " \
        "{%0,%1,%2,%3}, {%4,%5,%6,%7}, {%8,%9}, {%0,%1,%2,%3};" \
        : "+f"((C)[0]), "+f"((C)[1]), "+f"((C)[2]), "+f"((C)[3]) \
        : "r"(A0), "r"(A1), "r"(A2), "r"(A3), "r"(B0), "r"(B1))

__device__ __forceinline__ float blockReduceSum(float v, float* sm) {
    int lane = threadIdx.x & 31, wid = threadIdx.x >> 5;
    #pragma unroll
    for (int o = 16; o > 0; o >>= 1) v += __shfl_xor_sync(0xffffffffu, v, o);
    if (lane == 0) sm[wid] = v;
    __syncthreads();
    if (threadIdx.x < 32) {
        float t = (threadIdx.x < 8) ? sm[threadIdx.x] : 0.f;
        #pragma unroll
        for (int o = 4; o > 0; o >>= 1) t += __shfl_xor_sync(0xffffffffu, t, o);
        if (threadIdx.x == 0) sm[0] = t;
    }
    __syncthreads();
    float r = sm[0];
    __syncthreads();
    return r;
}

// ---------------- weight tf32 pre-round ----------------
__global__ __launch_bounds__(256)
void cvtw_kernel(const float4* __restrict__ src, float4* __restrict__ dst, int n4) {
    int i = blockIdx.x * 256 + threadIdx.x;
    if (i < n4) {
        float4 v = src[i];
        dst[i] = make_float4(tfv(v.x), tfv(v.y), tfv(v.z), tfv(v.w));
    }
}

// ---------------- embedding gather ----------------
__global__ void embed_kernel(const int* __restrict__ x,
                             const float* __restrict__ emb,
                             float* __restrict__ h) {
    int t = blockIdx.x;
    int tok = x[t];
    ((float4*)(h + (size_t)t*Dn))[threadIdx.x] =
        ((const float4*)(emb + (size_t)tok*Dn))[threadIdx.x];
}

// ---------------- LayerNorm (optionally fused double LN); output tf32-rounded ----------------
__global__ __launch_bounds__(256)
void ln_kernel(const float* __restrict__ x,
               const float* __restrict__ g,  const float* __restrict__ b,
               const float* __restrict__ g2, const float* __restrict__ b2,
               float* __restrict__ y, int dbl) {
    __shared__ float sm[32];
    int row = blockIdx.x;
    float4 v = ((const float4*)(x + (size_t)row*Dn))[threadIdx.x];
    float s  = v.x + v.y + v.z + v.w;
    float ss = v.x*v.x + v.y*v.y + v.z*v.z + v.w*v.w;
    float sum   = blockReduceSum(s, sm);
    float sumsq = blockReduceSum(ss, sm);
    float mean = sum * (1.f/Dn);
    float var  = sumsq * (1.f/Dn) - mean*mean;
    float r = rsqrtf(var + 1e-5f);
    int c = threadIdx.x * 4;
    float4 gv = *(const float4*)(g + c);
    float4 bv = *(const float4*)(b + c);
    float4 o;
    o.x = (v.x - mean)*r*gv.x + bv.x;
    o.y = (v.y - mean)*r*gv.y + bv.y;
    o.z = (v.z - mean)*r*gv.z + bv.z;
    o.w = (v.w - mean)*r*gv.w + bv.w;
    if (dbl) {
        s  = o.x + o.y + o.z + o.w;
        ss = o.x*o.x + o.y*o.y + o.z*o.z + o.w*o.w;
        sum   = blockReduceSum(s, sm);
        sumsq = blockReduceSum(ss, sm);
        mean = sum * (1.f/Dn);
        var  = sumsq * (1.f/Dn) - mean*mean;
        r = rsqrtf(var + 1e-5f);
        float4 g2v = *(const float4*)(g2 + c);
        float4 b2v = *(const float4*)(b2 + c);
        o.x = (o.x - mean)*r*g2v.x + b2v.x;
        o.y = (o.y - mean)*r*g2v.y + b2v.y;
        o.z = (o.z - mean)*r*g2v.z + b2v.z;
        o.w = (o.w - mean)*r*g2v.w + b2v.w;
    }
    o.x = tfv(o.x); o.y = tfv(o.y); o.z = tfv(o.z); o.w = tfv(o.w);
    ((float4*)(y + (size_t)row*Dn))[threadIdx.x] = o;
}

// ---------------- TF32 tensor-core GEMM, cp.async 4-stage pipeline (frozen) ----------------
// Inputs MUST be tf32-pre-rounded (mma truncation is then exact).
// If qh2 != null and blockIdx.z < 2: write ONLY packed bf16 hi/lo Q/K (no float C).
#define TBM 128
#define TBN 128
#define SA_PITCH 20
#define SB_PITCH 136
#define STG_A (128*SA_PITCH)
#define STG_B (16*SB_PITCH)
#define STG   (STG_A + STG_B)
#define TG_SMEM (4*STG*4)

__global__ __launch_bounds__(256, 2)
void tgemm_kernel(const float* __restrict__ A, const float* __restrict__ B,
                  const float* __restrict__ bias, const float* __restrict__ add,
                  float* __restrict__ C, int M, int N, int K,
                  int relu, int round_out, int swapxy,
                  size_t zB, size_t zBias, size_t zC,
                  uint32_t* __restrict__ qh2, uint32_t* __restrict__ ql2,
                  uint32_t* __restrict__ kh2, uint32_t* __restrict__ kl2) {
    extern __shared__ float smf[];

    B += (size_t)blockIdx.z * zB;
    if (bias) bias += (size_t)blockIdx.z * zBias;
    C += (size_t)blockIdx.z * zC;

    uint32_t* cvh = nullptr;
    uint32_t* cvl = nullptr;
    if (qh2) {
        if (blockIdx.z == 0)      { cvh = qh2; cvl = ql2; }
        else if (blockIdx.z == 1) { cvh = kh2; cvl = kl2; }
    }

    int tid  = threadIdx.x;
    int bxm = swapxy ? blockIdx.x : blockIdx.y;
    int bxn = swapxy ? blockIdx.y : blockIdx.x;
    int brow = bxm * TBM;
    int bcol = bxn * TBN;

    int warp = tid >> 5, lane = tid & 31;
    int gid = lane >> 2, tig = lane & 3;
    int warpM = (warp >> 2) * 64;
    int warpN = (warp & 3) * 32;

    const float* Ag = A + (size_t)brow * K;
    const float* Bg = B + bcol;

    int am0 = tid >> 1,          ak0 = (tid & 1) << 3;
    int bk0 = tid >> 5,          bn0 = (tid & 31) << 2;
    int bk1 = bk0 + 8;

    int nslab = K >> 4;
    auto issue = [&](int s) {
        float* As_ = smf + (s & 3) * STG;
        float* Bs_ = As_ + STG_A;
        int k0 = s << 4;
        const float* ag = Ag + (size_t)am0*K + k0 + ak0;
        cp16(As_ + am0*SA_PITCH + ak0,     ag);
        cp16(As_ + am0*SA_PITCH + ak0 + 4, ag + 4);
        cp16(Bs_ + bk0*SB_PITCH + bn0, Bg + (size_t)(k0+bk0)*N + bn0);
        cp16(Bs_ + bk1*SB_PITCH + bn0, Bg + (size_t)(k0+bk1)*N + bn0);
    };

    issue(0); CP_COMMIT;
    issue(1); CP_COMMIT;
    issue(2); CP_COMMIT;

    float acc[4][4][4] = {};

    for (int i = 0; i < nslab; i++) {
        asm volatile("cp.async.wait_group 2;" ::: "memory");
        __syncthreads();
        const float* As_ = smf + (i & 3) * STG;
        const float* Bs_ = As_ + STG_A;
        #pragma unroll
        for (int ks = 0; ks < 2; ks++) {
            int kb = ks * 8;
            uint32_t af[4][4], bf[4][2];
            #pragma unroll
            for (int mt = 0; mt < 4; mt++) {
                int r = warpM + mt*16 + gid;
                af[mt][0] = __float_as_uint(As_[(size_t)r    *SA_PITCH + kb + tig    ]);
                af[mt][1] = __float_as_uint(As_[(size_t)(r+8)*SA_PITCH + kb + tig    ]);
                af[mt][2] = __float_as_uint(As_[(size_t)r    *SA_PITCH + kb + tig + 4]);
                af[mt][3] = __float_as_uint(As_[(size_t)(r+8)*SA_PITCH + kb + tig + 4]);
            }
            #pragma unroll
            for (int nt = 0; nt < 4; nt++) {
                int c = warpN + nt*8 + gid;
                bf[nt][0] = __float_as_uint(Bs_[(size_t)(kb+tig  )*SB_PITCH + c]);
                bf[nt][1] = __float_as_uint(Bs_[(size_t)(kb+tig+4)*SB_PITCH + c]);
            }
            #pragma unroll
            for (int mt = 0; mt < 4; mt++)
                #pragma unroll
                for (int nt = 0; nt < 4; nt++)
                    MMA_TF32(acc[mt][nt], af[mt][0], af[mt][1], af[mt][2], af[mt][3],
                             bf[nt][0], bf[nt][1]);
        }
        if (i + 3 < nslab) issue(i + 3);
        CP_COMMIT;
    }

    #pragma unroll
    for (int mt = 0; mt < 4; mt++) {
        int r0 = brow + warpM + mt*16 + gid;
        int r1 = r0 + 8;
        #pragma unroll
        for (int nt = 0; nt < 4; nt++) {
            int c = bcol + warpN + nt*8 + tig*2;
            float v00 = acc[mt][nt][0], v01 = acc[mt][nt][1];
            float v10 = acc[mt][nt][2], v11 = acc[mt][nt][3];
            if (bias) {
                float bb0 = bias[c], bb1 = bias[c+1];
                v00 += bb0; v01 += bb1; v10 += bb0; v11 += bb1;
            }
            if (relu) {
                v00 = fmaxf(v00, 0.f); v01 = fmaxf(v01, 0.f);
                v10 = fmaxf(v10, 0.f); v11 = fmaxf(v11, 0.f);
            }
            if (round_out) {
                v00 = tfv(v00); v01 = tfv(v01);
                v10 = tfv(v10); v11 = tfv(v11);
            }
            if (add) {
                const float* ad0 = add + (size_t)r0*N + c;
                const float* ad1 = add + (size_t)r1*N + c;
                v00 += ad0[0]; v01 += ad0[1];
                v10 += ad1[0]; v11 += ad1[1];
            }
            if (cvh) {
                // Q/K: store packed bf16 hi/lo ONLY (float C never consumed)
                int hh = c >> 7, hdp = (c & 127) >> 1;
                int bb0_ = r0 >> 11, ss0 = r0 & 2047;
                int bb1_ = r1 >> 11, ss1 = r1 & 2047;
                size_t o0 = ((size_t)(bb0_*Hn + hh)*Sn + ss0)*64 + hdp;
                size_t o1 = ((size_t)(bb1_*Hn + hh)*Sn + ss1)*64 + hdp;
                uint32_t hi, lo;
                cvt_pair(v00, v01, hi, lo);
                cvh[o0] = hi; cvl[o0] = lo;
                cvt_pair(v10, v11, hi, lo);
                cvh[o1] = hi; cvl[o1] = lo;
            } else {
                *(float2*)(C + (size_t)r0*N + c) = make_float2(v00, v01);
                *(float2*)(C + (size_t)r1*N + c) = make_float2(v10, v11);
            }
        }
    }
}

// ---------------- rel-pos bias table (layer-invariant) ----------------
__global__ void bias_init_kernel(const float* __restrict__ rel,
                                 float* __restrict__ biasn) {
    int n = blockIdx.x * 256 + threadIdx.x;
    if (n >= Sn) return;
    float inv_log8 = 1.0f / logf(8.0f);
    int bucket;
    if (n < 16) bucket = n;
    else {
        int vb = 16 + (int)((logf((float)n * (1.0f/16.0f)) * inv_log8) * 16.0f);
        bucket = vb < 31 ? vb : 31;
    }
    for (int h = 0; h < Hn; h++)
        biasn[h*Sn + n] = rel[bucket*Hn + h] * SCALE_;
}

// ---------------- convert V transposed: [bh][hd][kv pairs] ----------------
__global__ __launch_bounds__(256)
void cvt_v_kernel(const float* __restrict__ v,
                  uint32_t* __restrict__ vh2T, uint32_t* __restrict__ vl2T) {
    __shared__ float vs[64][129];
    int kv0 = blockIdx.x * 64;
    int bh = blockIdx.y, b = bh >> 3, h = bh & 7;
    const float* vb = v + ((size_t)b*Sn + kv0)*Dn + h*HDn;
    for (int idx = threadIdx.x; idx < 64*32; idx += 256) {
        int r = idx >> 5, c4 = (idx & 31) << 2;
        float4 t = *(const float4*)(vb + (size_t)r*Dn + c4);
        vs[r][c4] = t.x; vs[r][c4+1] = t.y; vs[r][c4+2] = t.z; vs[r][c4+3] = t.w;
    }
    __syncthreads();
    int hd  = threadIdx.x >> 1;
    int kp0 = (threadIdx.x & 1) * 16;
    uint32_t* oh = vh2T + ((size_t)bh*HDn + hd)*(Sn/2) + (kv0 >> 1) + kp0;
    uint32_t* ol = vl2T + ((size_t)bh*HDn + hd)*(Sn/2) + (kv0 >> 1) + kp0;
    for (int kp = 0; kp < 16; kp++) {
        float f0 = vs[2*(kp0+kp)  ][hd];
        float f1 = vs[2*(kp0+kp)+1][hd];
        uint32_t hi, lo;
        cvt_pair(f0, f1, hi, lo);
        oh[kp] = hi; ol[kp] = lo;
    }
}

// ---------------- fused flash attention ----------------
#define FQP 68
#define FVP 36
#define FSM_U32 (4*64*FQP + 2*128*FVP)
#define FLASH_SMEM ((FSM_U32 + 512) * 4)

__global__ __launch_bounds__(256)
void flash_kernel(const uint32_t* __restrict__ qh2, const uint32_t* __restrict__ ql2,
                  const uint32_t* __restrict__ kh2, const uint32_t* __restrict__ kl2,
                  const uint32_t* __restrict__ vh2T, const uint32_t* __restrict__ vl2T,
                  const float* __restrict__ biasn, float* __restrict__ out) {
    extern __shared__ uint32_t smu[];
    uint32_t* qh  = smu;
    uint32_t* ql  = smu + 64*FQP;
    uint32_t* khb = smu + 2*64*FQP;
    uint32_t* klb = smu + 3*64*FQP;
    uint32_t* vhb = smu + 4*64*FQP;
    uint32_t* vlb = vhb + 128*FVP;
    float* m_s    = (float*)(vlb + 128*FVP);
    float* l_s    = m_s + 64;
    float* rmax   = l_s + 64;
    float* rsum   = rmax + 128;
    float* bias_s = rsum + 128;

    int ti = gridDim.x - 1 - (int)blockIdx.x;
    int bh = blockIdx.y, b = bh >> 3, h = bh & 7;
    int tid = threadIdx.x;
    int warp = tid >> 5, lane = tid & 31;
    int g = lane >> 2, t = lane & 3;
    int warpM  = (warp & 3) << 4;
    int grp    = warp >> 2;
    int warpNS = grp << 5;
    int warpNV = grp << 6;

    {
        size_t qoff = ((size_t)bh*Sn + (size_t)ti*64)*64;
        for (int idx = tid; idx < 1024; idx += 256) {
            int r = idx >> 4, c4 = (idx & 15) << 2;
            *(uint4*)&qh[r*FQP + c4] = *(const uint4*)(qh2 + qoff + (size_t)r*64 + c4);
            *(uint4*)&ql[r*FQP + c4] = *(const uint4*)(ql2 + qoff + (size_t)r*64 + c4);
        }
        if (tid < 64) { m_s[tid] = -INFINITY; l_s[tid] = 0.f; }
    }

    float acc[8][4] = {};
    int iloc0 = warpM + g;

    for (int jt = 0; jt <= ti; jt++) {
        __syncthreads();
        size_t koff = ((size_t)bh*Sn + (size_t)jt*64)*64;
        for (int idx = tid; idx < 1024; idx += 256) {
            int r = idx >> 4, c4 = (idx & 15) << 2;
            *(uint4*)&khb[r*FQP + c4] = *(const uint4*)(kh2 + koff + (size_t)r*64 + c4);
            *(uint4*)&klb[r*FQP + c4] = *(const uint4*)(kl2 + koff + (size_t)r*64 + c4);
        }
        size_t voff = (size_t)bh*HDn*(Sn/2) + (size_t)jt*32;
        for (int idx = tid; idx < 1024; idx += 256) {
            int r = idx >> 3, c4 = (idx & 7) << 2;
            *(uint4*)&vhb[r*FVP + c4] = *(const uint4*)(vh2T + voff + (size_t)r*(Sn/2) + c4);
            *(uint4*)&vlb[r*FVP + c4] = *(const uint4*)(vl2T + voff + (size_t)r*(Sn/2) + c4);
        }
        if (tid < 128) {
            int n = (ti - jt)*64 - 63 + tid;
            bias_s[tid] = biasn[h*Sn + (n > 0 ? n : 0)];
        }
        __syncthreads();

        float sacc[4][4] = {};
        #pragma unroll
        for (int ks = 0; ks < 8; ks++) {
            int c0 = 8*ks + t, c1 = c0 + 4;
            int rA = iloc0*FQP;
            uint32_t ah0 = qh[rA + c0],           ah1 = qh[rA + 8*FQP + c0];
            uint32_t ah2 = qh[rA + c1],           ah3 = qh[rA + 8*FQP + c1];
            uint32_t al0 = ql[rA + c0],           al1 = ql[rA + 8*FQP + c0];
            uint32_t al2 = ql[rA + c1],           al3 = ql[rA + 8*FQP + c1];
            #pragma unroll
            for (int nt = 0; nt < 4; nt++) {
                int rB = (warpNS + nt*8 + g)*FQP;
                uint32_t kb0 = khb[rB + c0], kb1 = khb[rB + c1];
                uint32_t kc0 = klb[rB + c0], kc1 = klb[rB + c1];
                MMA_BF16(sacc[nt], ah0, ah1, ah2, ah3, kb0, kb1);
                MMA_BF16(sacc[nt], ah0, ah1, ah2, ah3, kc0, kc1);
                MMA_BF16(sacc[nt], al0, al1, al2, al3, kb0, kb1);
            }
        }

        int i0 = ti*64 + iloc0;
        #pragma unroll
        for (int nt = 0; nt < 4; nt++) {
            int jloc = warpNS + nt*8 + 2*t;
            int j0 = jt*64 + jloc;
            int d00 = iloc0 - jloc + 63;
            sacc[nt][0] = (j0     <= i0    ) ? (sacc[nt][0] + bias_s[d00    ]) * SCALE_ : -INFINITY;
            sacc[nt][1] = (j0 + 1 <= i0    ) ? (sacc[nt][1] + bias_s[d00 - 1]) * SCALE_ : -INFINITY;
            sacc[nt][2] = (j0     <= i0 + 8) ? (sacc[nt][2] + bias_s[d00 + 8]) * SCALE_ : -INFINITY;
            sacc[nt][3] = (j0 + 1 <= i0 + 8) ? (sacc[nt][3] + bias_s[d00 + 7]) * SCALE_ : -INFINITY;
        }

        float mx0 = fmaxf(fmaxf(sacc[0][0], sacc[0][1]), fmaxf(sacc[1][0], sacc[1][1]));
        mx0 = fmaxf(mx0, fmaxf(fmaxf(sacc[2][0], sacc[2][1]), fmaxf(sacc[3][0], sacc[3][1])));
        float mx1 = fmaxf(fmaxf(sacc[0][2], sacc[0][3]), fmaxf(sacc[1][2], sacc[1][3]));
        mx1 = fmaxf(mx1, fmaxf(fmaxf(sacc[2][2], sacc[2][3]), fmaxf(sacc[3][2], sacc[3][3])));
        mx0 = fmaxf(mx0, __shfl_xor_sync(0xffffffffu, mx0, 1));
        mx0 = fmaxf(mx0, __shfl_xor_sync(0xffffffffu, mx0, 2));
        mx1 = fmaxf(mx1, __shfl_xor_sync(0xffffffffu, mx1, 1));
        mx1 = fmaxf(mx1, __shfl_xor_sync(0xffffffffu, mx1, 2));
        if (t == 0) {
            rmax[grp*64 + iloc0]     = mx0;
            rmax[grp*64 + iloc0 + 8] = mx1;
        }
        __syncthreads();

        float mold0 = m_s[iloc0], mold1 = m_s[iloc0 + 8];
        float mnew0 = fmaxf(mold0, fmaxf(rmax[iloc0],     rmax[64 + iloc0]));
        float mnew1 = fmaxf(mold1, fmaxf(rmax[iloc0 + 8], rmax[64 + iloc0 + 8]));
        float fac0 = __expf(mold0 - mnew0);
        float fac1 = __expf(mold1 - mnew1);

        float sum0 = 0.f, sum1 = 0.f;
        #pragma unroll
        for (int nt = 0; nt < 4; nt++) {
            float p00 = __expf(sacc[nt][0] - mnew0);
            float p01 = __expf(sacc[nt][1] - mnew0);
            float p10 = __expf(sacc[nt][2] - mnew1);
            float p11 = __expf(sacc[nt][3] - mnew1);
            sum0 += p00 + p01; sum1 += p10 + p11;
            int cc = (warpNS >> 1) + nt*4 + t;
            uint32_t hi, lo;
            cvt_pair(p00, p01, hi, lo);
            khb[iloc0*FQP + cc] = hi; klb[iloc0*FQP + cc] = lo;
            cvt_pair(p10, p11, hi, lo);
            khb[(iloc0+8)*FQP + cc] = hi; klb[(iloc0+8)*FQP + cc] = lo;
        }
        sum0 += __shfl_xor_sync(0xffffffffu, sum0, 1);
        sum0 += __shfl_xor_sync(0xffffffffu, sum0, 2);
        sum1 += __shfl_xor_sync(0xffffffffu, sum1, 1);
        sum1 += __shfl_xor_sync(0xffffffffu, sum1, 2);
        if (t == 0) {
            rsum[grp*64 + iloc0]     = sum0;
            rsum[grp*64 + iloc0 + 8] = sum1;
        }

        #pragma unroll
        for (int nt = 0; nt < 8; nt++) {
            acc[nt][0] *= fac0; acc[nt][1] *= fac0;
            acc[nt][2] *= fac1; acc[nt][3] *= fac1;
        }
        __syncthreads();

        if (tid < 64) {
            float mo = m_s[tid];
            float mn = fmaxf(mo, fmaxf(rmax[tid], rmax[64 + tid]));
            l_s[tid] = l_s[tid] * __expf(mo - mn) + rsum[tid] + rsum[64 + tid];
            m_s[tid] = mn;
        }

        #pragma unroll
        for (int ks = 0; ks < 4; ks++) {
            int c0 = 8*ks + t, c1 = c0 + 4;
            int rA = iloc0*FQP;
            uint32_t ah0 = khb[rA + c0],           ah1 = khb[rA + 8*FQP + c0];
            uint32_t ah2 = khb[rA + c1],           ah3 = khb[rA + 8*FQP + c1];
            uint32_t al0 = klb[rA + c0],           al1 = klb[rA + 8*FQP + c0];
            uint32_t al2 = klb[rA + c1],           al3 = klb[rA + 8*FQP + c1];
            #pragma unroll
            for (int nt = 0; nt < 8; nt++) {
                int rB = (warpNV + nt*8 + g)*FVP;
                uint32_t vb0 = vhb[rB + c0], vb1 = vhb[rB + c1];
                uint32_t vc0 = vlb[rB + c0], vc1 = vlb[rB + c1];
                MMA_BF16(acc[nt], ah0, ah1, ah2, ah3, vb0, vb1);
                MMA_BF16(acc[nt], ah0, ah1, ah2, ah3, vc0, vc1);
                MMA_BF16(acc[nt], al0, al1, al2, al3, vb0, vb1);
            }
        }
    }

    __syncthreads();
    float inv0 = 1.f / l_s[iloc0];
    float inv1 = 1.f / l_s[iloc0 + 8];
    int i0 = ti*64 + iloc0;
    #pragma unroll
    for (int nt = 0; nt < 8; nt++) {
        int col = warpNV + nt*8 + 2*t;
        float* op0 = out + ((size_t)b*Sn + i0)*Dn + h*HDn + col;
        float* op1 = op0 + 8*(size_t)Dn;
        *(float2*)op0 = make_float2(tfv(acc[nt][0]*inv0), tfv(acc[nt][1]*inv0));
        *(float2*)op1 = make_float2(tfv(acc[nt][2]*inv1), tfv(acc[nt][3]*inv1));
    }
}

// ---------------- orchestration ----------------
extern "C" void kernel_launch(void* const* d_in, const int* in_sizes, int n_in,
                              void* d_out, int out_size) {
    (void)in_sizes; (void)n_in; (void)out_size;
    const int*   x     = (const int*)  d_in[0];
    const float* tok   = (const float*)d_in[1];
    const float* rel   = (const float*)d_in[2];
    const float* ln_g  = (const float*)d_in[3];
    const float* ln_b  = (const float*)d_in[4];
    const float* Wqkv  = (const float*)d_in[5];
    const float* bqkv  = (const float*)d_in[6];
    const float* Wo    = (const float*)d_in[7];
    const float* bo    = (const float*)d_in[8];
    const float* W1    = (const float*)d_in[9];
    const float* b1    = (const float*)d_in[10];
    const float* W2    = (const float*)d_in[11];
    const float* b2    = (const float*)d_in[12];
    const float* lnf_g = (const float*)d_in[13];
    const float* lnf_b = (const float*)d_in[14];
    const float* Whead = (const float*)d_in[15];
    const float* bhead = (const float*)d_in[16];
    float* out = (float*)d_out;

    float *h, *ln, *qkv, *ao, *mid, *biasn, *w;
    uint32_t *qh2, *ql2, *kh2, *kl2, *vh2T, *vl2T;
    cudaGetSymbolAddress((void**)&h,    g_h);
    cudaGetSymbolAddress((void**)&ln,   g_ln);
    cudaGetSymbolAddress((void**)&qkv,  g_qkv);
    cudaGetSymbolAddress((void**)&ao,   g_ao);
    cudaGetSymbolAddress((void**)&mid,  g_mid);
    cudaGetSymbolAddress((void**)&biasn,g_biasn);
    cudaGetSymbolAddress((void**)&w,    g_w);
    cudaGetSymbolAddress((void**)&qh2,  g_qh2);
    cudaGetSymbolAddress((void**)&ql2,  g_ql2);
    cudaGetSymbolAddress((void**)&kh2,  g_kh2);
    cudaGetSymbolAddress((void**)&kl2,  g_kl2);
    cudaGetSymbolAddress((void**)&vh2T, g_vh2T);
    cudaGetSymbolAddress((void**)&vl2T, g_vl2T);

    cudaFuncSetAttribute(flash_kernel, cudaFuncAttributeMaxDynamicSharedMemorySize,
                         FLASH_SMEM);
    cudaFuncSetAttribute(tgemm_kernel, cudaFuncAttributeMaxDynamicSharedMemorySize,
                         TG_SMEM);

    // pre-round all weights to tf32 (serial; ~105us total)
    {
        struct { const float* s; float* d; size_t n; } cv[5] = {
            { Wqkv,  w + OFF_WQKV,  (size_t)Ln*3*Dn*Dn },
            { Wo,    w + OFF_WO,    (size_t)Ln*Dn*Dn   },
            { W1,    w + OFF_W1,    (size_t)Ln*Dn*FFn  },
            { W2,    w + OFF_W2,    (size_t)Ln*FFn*Dn  },
            { Whead, w + OFF_WHEAD, (size_t)Dn*Vn      },
        };
        for (int i = 0; i < 5; i++) {
            int n4 = (int)(cv[i].n >> 2);
            cvtw_kernel<<<(n4 + 255)/256, 256>>>((const float4*)cv[i].s,
                                                 (float4*)cv[i].d, n4);
        }
    }

    const float* v = qkv + (size_t)2*Mtok*Dn;

    embed_kernel<<<Mtok, 256>>>(x, tok, h);
    bias_init_kernel<<<Sn/256, 256>>>(rel, biasn);

    dim3 gDD(Dn/TBN,  Mtok/TBM);
    dim3 gQKV(Dn/TBN, Mtok/TBM, 3);
    dim3 gDF(FFn/TBN, Mtok/TBM);
    dim3 gDV(Mtok/TBM, Vn/TBN);           // M-fastest for the huge-N head GEMM

    for (int l = 0; l < Ln; l++) {
        ln_kernel<<<Mtok, 256>>>(h, ln_g + (size_t)(l*3+0)*Dn, ln_b + (size_t)(l*3+0)*Dn,
                                 nullptr, nullptr, ln, 0);
        // QKV: z=0/1 write packed Q/K directly (no float C); z=2 writes float V
        tgemm_kernel<<<gQKV, 256, TG_SMEM>>>(ln, w + OFF_WQKV + (size_t)l*3*Dn*Dn,
                                    bqkv + (size_t)l*3*Dn, nullptr, qkv,
                                    Mtok, Dn, Dn, 0, 0, 0,
                                    (size_t)Dn*Dn, (size_t)Dn, (size_t)Mtok*Dn,
                                    qh2, ql2, kh2, kl2);
        cvt_v_kernel<<<dim3(Sn/64, Bn*Hn), 256>>>(v, vh2T, vl2T);
        flash_kernel<<<dim3(Sn/64, Bn*Hn), 256, FLASH_SMEM>>>(
            qh2, ql2, kh2, kl2, vh2T, vl2T, biasn, ao);
        tgemm_kernel<<<gDD, 256, TG_SMEM>>>(ao, w + OFF_WO + (size_t)l*Dn*Dn,
                                   bo + (size_t)l*Dn, h, h,
                                   Mtok, Dn, Dn, 0, 0, 0, 0, 0, 0,
                                   nullptr, nullptr, nullptr, nullptr);
        ln_kernel<<<Mtok, 256>>>(h, ln_g + (size_t)(l*3+1)*Dn, ln_b + (size_t)(l*3+1)*Dn,
                                 ln_g + (size_t)(l*3+2)*Dn, ln_b + (size_t)(l*3+2)*Dn, ln, 1);
        tgemm_kernel<<<gDF, 256, TG_SMEM>>>(ln, w + OFF_W1 + (size_t)l*Dn*FFn,
                                   b1 + (size_t)l*FFn, nullptr, mid,
                                   Mtok, FFn, Dn, 1, 1, 0, 0, 0, 0,
                                   nullptr, nullptr, nullptr, nullptr);
        tgemm_kernel<<<gDD, 256, TG_SMEM>>>(mid, w + OFF_W2 + (size_t)l*FFn*Dn,
                                   b2 + (size_t)l*Dn, h, h,
                                   Mtok, Dn, FFn, 0, 0, 0, 0, 0, 0,
                                   nullptr, nullptr, nullptr, nullptr);
    }

    ln_kernel<<<Mtok, 256>>>(h, lnf_g, lnf_b, nullptr, nullptr, ln, 0);
    tgemm_kernel<<<gDV, 256, TG_SMEM>>>(ln, w + OFF_WHEAD, bhead, nullptr, out,
                               Mtok, Vn, Dn, 0, 0, 1, 0, 0, 0,
                               nullptr, nullptr, nullptr, nullptr);
}

// round 15
// speedup vs baseline: 1.0388x; 1.0377x over previous
#include <cuda_runtime.h>
#include <cuda_bf16.h>
#include <math.h>
#include <stdint.h>

// ---------------- problem constants ----------------
#define Bn   2
#define Sn   2048
#define Dn   1024
#define Hn   8
#define HDn  128
#define Vn   32000
#define Ln   6
#define Mtok (Bn*Sn)      // 4096
#define FFn  (4*Dn)       // 4096
#define SCALE_ 0.08838834764831845f   // 128^-0.5

// ---------------- scratch (device globals; no cudaMalloc allowed) ----------------
__device__ float g_h  [(size_t)Mtok*Dn];
__device__ float g_ln [(size_t)Mtok*Dn];
__device__ float g_qkv[(size_t)3*Mtok*Dn];
__device__ float g_ao [(size_t)Mtok*Dn];
__device__ float g_mid[(size_t)Mtok*FFn];
__device__ uint32_t g_qh2[(size_t)Bn*Hn*Sn*64];
__device__ uint32_t g_ql2[(size_t)Bn*Hn*Sn*64];
__device__ uint32_t g_kh2[(size_t)Bn*Hn*Sn*64];
__device__ uint32_t g_kl2[(size_t)Bn*Hn*Sn*64];
__device__ uint32_t g_vh2T[(size_t)Bn*Hn*HDn*(Sn/2)];
__device__ uint32_t g_vl2T[(size_t)Bn*Hn*HDn*(Sn/2)];
__device__ float g_biasn[Hn*Sn];
// tf32-pre-rounded weights ([K][N], same layout as inputs)
#define OFF_WQKV ((size_t)0)
#define OFF_WO   (OFF_WQKV + (size_t)Ln*3*Dn*Dn)
#define OFF_W1   (OFF_WO   + (size_t)Ln*Dn*Dn)
#define OFF_W2   (OFF_W1   + (size_t)Ln*Dn*FFn)
#define OFF_WHEAD (OFF_W2  + (size_t)Ln*FFn*Dn)
#define NW_TOTAL (OFF_WHEAD + (size_t)Dn*Vn)
__device__ float g_w[NW_TOTAL];

// ---------------- helpers ----------------
__device__ __forceinline__ uint32_t f2tf32(float f) {
    uint32_t u;
    asm("cvt.rna.tf32.f32 %0, %1;" : "=r"(u) : "f"(f));
    return u;
}
__device__ __forceinline__ float tfv(float f) { return __uint_as_float(f2tf32(f)); }

__device__ __forceinline__ void cp16(void* dst_smem, const void* src) {
    uint32_t d = (uint32_t)__cvta_generic_to_shared(dst_smem);
    asm volatile("cp.async.cg.shared.global [%0], [%1], 16;" :: "r"(d), "l"(src));
}
#define CP_COMMIT asm volatile("cp.async.commit_group;" ::: "memory")

// split f0,f1 into bf16 hi/lo pairs packed as b32 (low half = first element)
__device__ __forceinline__ void cvt_pair(float f0, float f1, uint32_t& hi, uint32_t& lo) {
    __nv_bfloat16 h0 = __float2bfloat16(f0);
    __nv_bfloat16 h1 = __float2bfloat16(f1);
    __nv_bfloat16 l0 = __float2bfloat16(f0 - __bfloat162float(h0));
    __nv_bfloat16 l1 = __float2bfloat16(f1 - __bfloat162float(h1));
    hi = ((uint32_t)__bfloat16_as_ushort(h1) << 16) | (uint32_t)__bfloat16_as_ushort(h0);
    lo = ((uint32_t)__bfloat16_as_ushort(l1) << 16) | (uint32_t)__bfloat16_as_ushort(l0);
}

#define MMA_BF16(C, A0,A1,A2,A3, B0,B1) \
    asm volatile("mma.sync.aligned.m16n8k16.row.col.f32.bf16.bf16.f32 " \
        "{%0,%1,%2,%3}, {%4,%5,%6,%7}, {%8,%9}, {%0,%1,%2,%3};" \
        : "+f"((C)[0]), "+f"((C)[1]), "+f"((C)[2]), "+f"((C)[3]) \
        : "r"(A0), "r"(A1), "r"(A2), "r"(A3), "r"(B0), "r"(B1))

#define MMA_TF32(C, A0,A1,A2,A3, B0,B1) \
    asm volatile("mma.sync.aligned.m16n8k8.row.col.f32.tf32.tf32.f32 " \
        "{%0,%1,%2,%3}, {%4,%5,%6,%7}, {%8,%9}, {%0,%1,%2,%3};" \
        : "+f"((C)[0]), "+f"((C)[1]), "+f"((C)[2]), "+f"((C)[3]) \
        : "r"(A0), "r"(A1), "r"(A2), "r"(A3), "r"(B0), "r"(B1))

__device__ __forceinline__ float blockReduceSum(float v, float* sm) {
    int lane = threadIdx.x & 31, wid = threadIdx.x >> 5;
    #pragma unroll
    for (int o = 16; o > 0; o >>= 1) v += __shfl_xor_sync(0xffffffffu, v, o);
    if (lane == 0) sm[wid] = v;
    __syncthreads();
    if (threadIdx.x < 32) {
        float t = (threadIdx.x < 8) ? sm[threadIdx.x] : 0.f;
        #pragma unroll
        for (int o = 4; o > 0; o >>= 1) t += __shfl_xor_sync(0xffffffffu, t, o);
        if (threadIdx.x == 0) sm[0] = t;
    }
    __syncthreads();
    float r = sm[0];
    __syncthreads();
    return r;
}

// ---------------- weight tf32 pre-round ----------------
__global__ __launch_bounds__(256)
void cvtw_kernel(const float4* __restrict__ src, float4* __restrict__ dst, int n4) {
    int i = blockIdx.x * 256 + threadIdx.x;
    if (i < n4) {
        float4 v = src[i];
        dst[i] = make_float4(tfv(v.x), tfv(v.y), tfv(v.z), tfv(v.w));
    }
}

// ---------------- embedding gather ----------------
__global__ void embed_kernel(const int* __restrict__ x,
                             const float* __restrict__ emb,
                             float* __restrict__ h) {
    int t = blockIdx.x;
    int tok = x[t];
    ((float4*)(h + (size_t)t*Dn))[threadIdx.x] =
        ((const float4*)(emb + (size_t)tok*Dn))[threadIdx.x];
}

// ---------------- LayerNorm (optionally fused double LN); output tf32-rounded ----------------
__global__ __launch_bounds__(256)
void ln_kernel(const float* __restrict__ x,
               const float* __restrict__ g,  const float* __restrict__ b,
               const float* __restrict__ g2, const float* __restrict__ b2,
               float* __restrict__ y, int dbl) {
    __shared__ float sm[32];
    int row = blockIdx.x;
    float4 v = ((const float4*)(x + (size_t)row*Dn))[threadIdx.x];
    float s  = v.x + v.y + v.z + v.w;
    float ss = v.x*v.x + v.y*v.y + v.z*v.z + v.w*v.w;
    float sum   = blockReduceSum(s, sm);
    float sumsq = blockReduceSum(ss, sm);
    float mean = sum * (1.f/Dn);
    float var  = sumsq * (1.f/Dn) - mean*mean;
    float r = rsqrtf(var + 1e-5f);
    int c = threadIdx.x * 4;
    float4 gv = *(const float4*)(g + c);
    float4 bv = *(const float4*)(b + c);
    float4 o;
    o.x = (v.x - mean)*r*gv.x + bv.x;
    o.y = (v.y - mean)*r*gv.y + bv.y;
    o.z = (v.z - mean)*r*gv.z + bv.z;
    o.w = (v.w - mean)*r*gv.w + bv.w;
    if (dbl) {
        s  = o.x + o.y + o.z + o.w;
        ss = o.x*o.x + o.y*o.y + o.z*o.z + o.w*o.w;
        sum   = blockReduceSum(s, sm);
        sumsq = blockReduceSum(ss, sm);
        mean = sum * (1.f/Dn);
        var  = sumsq * (1.f/Dn) - mean*mean;
        r = rsqrtf(var + 1e-5f);
        float4 g2v = *(const float4*)(g2 + c);
        float4 b2v = *(const float4*)(b2 + c);
        o.x = (o.x - mean)*r*g2v.x + b2v.x;
        o.y = (o.y - mean)*r*g2v.y + b2v.y;
        o.z = (o.z - mean)*r*g2v.z + b2v.z;
        o.w = (o.w - mean)*r*g2v.w + b2v.w;
    }
    o.x = tfv(o.x); o.y = tfv(o.y); o.z = tfv(o.z); o.w = tfv(o.w);
    ((float4*)(y + (size_t)row*Dn))[threadIdx.x] = o;
}

// ---------------- TF32 tensor-core GEMM, cp.async 4-stage pipeline (frozen) ----------------
// Inputs MUST be tf32-pre-rounded (mma truncation is then exact).
// If qh2 != null and blockIdx.z < 2: write ONLY packed bf16 hi/lo Q/K (no float C).
#define TBM 128
#define TBN 128
#define SA_PITCH 20
#define SB_PITCH 136
#define STG_A (128*SA_PITCH)
#define STG_B (16*SB_PITCH)
#define STG   (STG_A + STG_B)
#define TG_SMEM (4*STG*4)

__global__ __launch_bounds__(256, 2)
void tgemm_kernel(const float* __restrict__ A, const float* __restrict__ B,
                  const float* __restrict__ bias, const float* __restrict__ add,
                  float* __restrict__ C, int M, int N, int K,
                  int relu, int round_out, int swapxy,
                  size_t zB, size_t zBias, size_t zC,
                  uint32_t* __restrict__ qh2, uint32_t* __restrict__ ql2,
                  uint32_t* __restrict__ kh2, uint32_t* __restrict__ kl2) {
    extern __shared__ float smf[];

    B += (size_t)blockIdx.z * zB;
    if (bias) bias += (size_t)blockIdx.z * zBias;
    C += (size_t)blockIdx.z * zC;

    uint32_t* cvh = nullptr;
    uint32_t* cvl = nullptr;
    if (qh2) {
        if (blockIdx.z == 0)      { cvh = qh2; cvl = ql2; }
        else if (blockIdx.z == 1) { cvh = kh2; cvl = kl2; }
    }

    int tid  = threadIdx.x;
    int bxm = swapxy ? blockIdx.x : blockIdx.y;
    int bxn = swapxy ? blockIdx.y : blockIdx.x;
    int brow = bxm * TBM;
    int bcol = bxn * TBN;

    int warp = tid >> 5, lane = tid & 31;
    int gid = lane >> 2, tig = lane & 3;
    int warpM = (warp >> 2) * 64;
    int warpN = (warp & 3) * 32;

    const float* Ag = A + (size_t)brow * K;
    const float* Bg = B + bcol;

    int am0 = tid >> 1,          ak0 = (tid & 1) << 3;
    int bk0 = tid >> 5,          bn0 = (tid & 31) << 2;
    int bk1 = bk0 + 8;

    int nslab = K >> 4;
    auto issue = [&](int s) {
        float* As_ = smf + (s & 3) * STG;
        float* Bs_ = As_ + STG_A;
        int k0 = s << 4;
        const float* ag = Ag + (size_t)am0*K + k0 + ak0;
        cp16(As_ + am0*SA_PITCH + ak0,     ag);
        cp16(As_ + am0*SA_PITCH + ak0 + 4, ag + 4);
        cp16(Bs_ + bk0*SB_PITCH + bn0, Bg + (size_t)(k0+bk0)*N + bn0);
        cp16(Bs_ + bk1*SB_PITCH + bn0, Bg + (size_t)(k0+bk1)*N + bn0);
    };

    issue(0); CP_COMMIT;
    issue(1); CP_COMMIT;
    issue(2); CP_COMMIT;

    float acc[4][4][4] = {};

    for (int i = 0; i < nslab; i++) {
        asm volatile("cp.async.wait_group 2;" ::: "memory");
        __syncthreads();
        const float* As_ = smf + (i & 3) * STG;
        const float* Bs_ = As_ + STG_A;
        #pragma unroll
        for (int ks = 0; ks < 2; ks++) {
            int kb = ks * 8;
            uint32_t af[4][4], bf[4][2];
            #pragma unroll
            for (int mt = 0; mt < 4; mt++) {
                int r = warpM + mt*16 + gid;
                af[mt][0] = __float_as_uint(As_[(size_t)r    *SA_PITCH + kb + tig    ]);
                af[mt][1] = __float_as_uint(As_[(size_t)(r+8)*SA_PITCH + kb + tig    ]);
                af[mt][2] = __float_as_uint(As_[(size_t)r    *SA_PITCH + kb + tig + 4]);
                af[mt][3] = __float_as_uint(As_[(size_t)(r+8)*SA_PITCH + kb + tig + 4]);
            }
            #pragma unroll
            for (int nt = 0; nt < 4; nt++) {
                int c = warpN + nt*8 + gid;
                bf[nt][0] = __float_as_uint(Bs_[(size_t)(kb+tig  )*SB_PITCH + c]);
                bf[nt][1] = __float_as_uint(Bs_[(size_t)(kb+tig+4)*SB_PITCH + c]);
            }
            #pragma unroll
            for (int mt = 0; mt < 4; mt++)
                #pragma unroll
                for (int nt = 0; nt < 4; nt++)
                    MMA_TF32(acc[mt][nt], af[mt][0], af[mt][1], af[mt][2], af[mt][3],
                             bf[nt][0], bf[nt][1]);
        }
        if (i + 3 < nslab) issue(i + 3);
        CP_COMMIT;
    }

    #pragma unroll
    for (int mt = 0; mt < 4; mt++) {
        int r0 = brow + warpM + mt*16 + gid;
        int r1 = r0 + 8;
        #pragma unroll
        for (int nt = 0; nt < 4; nt++) {
            int c = bcol + warpN + nt*8 + tig*2;
            float v00 = acc[mt][nt][0], v01 = acc[mt][nt][1];
            float v10 = acc[mt][nt][2], v11 = acc[mt][nt][3];
            if (bias) {
                float bb0 = bias[c], bb1 = bias[c+1];
                v00 += bb0; v01 += bb1; v10 += bb0; v11 += bb1;
            }
            if (relu) {
                v00 = fmaxf(v00, 0.f); v01 = fmaxf(v01, 0.f);
                v10 = fmaxf(v10, 0.f); v11 = fmaxf(v11, 0.f);
            }
            if (round_out) {
                v00 = tfv(v00); v01 = tfv(v01);
                v10 = tfv(v10); v11 = tfv(v11);
            }
            if (add) {
                const float* ad0 = add + (size_t)r0*N + c;
                const float* ad1 = add + (size_t)r1*N + c;
                v00 += ad0[0]; v01 += ad0[1];
                v10 += ad1[0]; v11 += ad1[1];
            }
            if (cvh) {
                int hh = c >> 7, hdp = (c & 127) >> 1;
                int bb0_ = r0 >> 11, ss0 = r0 & 2047;
                int bb1_ = r1 >> 11, ss1 = r1 & 2047;
                size_t o0 = ((size_t)(bb0_*Hn + hh)*Sn + ss0)*64 + hdp;
                size_t o1 = ((size_t)(bb1_*Hn + hh)*Sn + ss1)*64 + hdp;
                uint32_t hi, lo;
                cvt_pair(v00, v01, hi, lo);
                cvh[o0] = hi; cvl[o0] = lo;
                cvt_pair(v10, v11, hi, lo);
                cvh[o1] = hi; cvl[o1] = lo;
            } else {
                *(float2*)(C + (size_t)r0*N + c) = make_float2(v00, v01);
                *(float2*)(C + (size_t)r1*N + c) = make_float2(v10, v11);
            }
        }
    }
}

// ---------------- rel-pos bias table (layer-invariant) ----------------
__global__ void bias_init_kernel(const float* __restrict__ rel,
                                 float* __restrict__ biasn) {
    int n = blockIdx.x * 256 + threadIdx.x;
    if (n >= Sn) return;
    float inv_log8 = 1.0f / logf(8.0f);
    int bucket;
    if (n < 16) bucket = n;
    else {
        int vb = 16 + (int)((logf((float)n * (1.0f/16.0f)) * inv_log8) * 16.0f);
        bucket = vb < 31 ? vb : 31;
    }
    for (int h = 0; h < Hn; h++)
        biasn[h*Sn + n] = rel[bucket*Hn + h] * SCALE_;
}

// ---------------- convert V transposed: [bh][hd][kv pairs] ----------------
__global__ __launch_bounds__(256)
void cvt_v_kernel(const float* __restrict__ v,
                  uint32_t* __restrict__ vh2T, uint32_t* __restrict__ vl2T) {
    __shared__ float vs[64][129];
    int kv0 = blockIdx.x * 64;
    int bh = blockIdx.y, b = bh >> 3, h = bh & 7;
    const float* vb = v + ((size_t)b*Sn + kv0)*Dn + h*HDn;
    for (int idx = threadIdx.x; idx < 64*32; idx += 256) {
        int r = idx >> 5, c4 = (idx & 31) << 2;
        float4 t = *(const float4*)(vb + (size_t)r*Dn + c4);
        vs[r][c4] = t.x; vs[r][c4+1] = t.y; vs[r][c4+2] = t.z; vs[r][c4+3] = t.w;
    }
    __syncthreads();
    int hd  = threadIdx.x >> 1;
    int kp0 = (threadIdx.x & 1) * 16;
    uint32_t* oh = vh2T + ((size_t)bh*HDn + hd)*(Sn/2) + (kv0 >> 1) + kp0;
    uint32_t* ol = vl2T + ((size_t)bh*HDn + hd)*(Sn/2) + (kv0 >> 1) + kp0;
    for (int kp = 0; kp < 16; kp++) {
        float f0 = vs[2*(kp0+kp)  ][hd];
        float f1 = vs[2*(kp0+kp)+1][hd];
        uint32_t hi, lo;
        cvt_pair(f0, f1, hi, lo);
        oh[kp] = hi; ol[kp] = lo;
    }
}

// ---------------- fused flash attention (cp.async double-buffered K/V) ----------------
#define FQP 68
#define FVP 36
#define FPP 36
#define FSM_U32 (2*64*FQP + 4*64*FQP + 4*128*FVP + 2*64*FPP)
#define FLASH_SMEM ((FSM_U32 + 512) * 4)   // 198,656 bytes

__global__ __launch_bounds__(256)
void flash_kernel(const uint32_t* __restrict__ qh2, const uint32_t* __restrict__ ql2,
                  const uint32_t* __restrict__ kh2, const uint32_t* __restrict__ kl2,
                  const uint32_t* __restrict__ vh2T, const uint32_t* __restrict__ vl2T,
                  const float* __restrict__ biasn, float* __restrict__ out) {
    extern __shared__ uint32_t smu[];
    uint32_t* qh  = smu;
    uint32_t* ql  = smu + 64*FQP;
    uint32_t* khS = smu + 2*64*FQP;          // 2 stages of 64*FQP
    uint32_t* klS = khS + 2*64*FQP;
    uint32_t* vhS = klS + 2*64*FQP;          // 2 stages of 128*FVP
    uint32_t* vlS = vhS + 2*128*FVP;
    uint32_t* ph  = vlS + 2*128*FVP;         // P hi (64*FPP)
    uint32_t* pl  = ph + 64*FPP;
    float* m_s    = (float*)(pl + 64*FPP);
    float* l_s    = m_s + 64;
    float* rmax   = l_s + 64;
    float* rsum   = rmax + 128;
    float* bias_s = rsum + 128;

    int ti = gridDim.x - 1 - (int)blockIdx.x;
    int bh = blockIdx.y, b = bh >> 3, h = bh & 7;
    int tid = threadIdx.x;
    int warp = tid >> 5, lane = tid & 31;
    int g = lane >> 2, t = lane & 3;
    int warpM  = (warp & 3) << 4;
    int grp    = warp >> 2;
    int warpNS = grp << 5;
    int warpNV = grp << 6;

    auto issueKV = [&](int jt) {
        int st = jt & 1;
        uint32_t* kh_ = khS + st*64*FQP;
        uint32_t* kl_ = klS + st*64*FQP;
        uint32_t* vh_ = vhS + st*128*FVP;
        uint32_t* vl_ = vlS + st*128*FVP;
        size_t koff = ((size_t)bh*Sn + (size_t)jt*64)*64;
        #pragma unroll
        for (int i = 0; i < 4; i++) {           // K: 64 rows x 16 chunks = 1024 chunks
            int c = tid + (i << 8);
            int r = c >> 4, o4 = (c & 15) << 2;
            cp16(kh_ + r*FQP + o4, kh2 + koff + (size_t)r*64 + o4);
            cp16(kl_ + r*FQP + o4, kl2 + koff + (size_t)r*64 + o4);
        }
        size_t voff = (size_t)bh*HDn*(Sn/2) + (size_t)jt*32;
        #pragma unroll
        for (int i = 0; i < 4; i++) {           // V: 128 rows x 8 chunks = 1024 chunks
            int c = tid + (i << 8);
            int r = c >> 3, o4 = (c & 7) << 2;
            cp16(vh_ + r*FVP + o4, vh2T + voff + (size_t)r*(Sn/2) + o4);
            cp16(vl_ + r*FVP + o4, vl2T + voff + (size_t)r*(Sn/2) + o4);
        }
    };

    // prologue: start K/V(0), stage Q, init stats
    issueKV(0); CP_COMMIT;
    {
        size_t qoff = ((size_t)bh*Sn + (size_t)ti*64)*64;
        for (int idx = tid; idx < 1024; idx += 256) {
            int r = idx >> 4, c4 = (idx & 15) << 2;
            *(uint4*)&qh[r*FQP + c4] = *(const uint4*)(qh2 + qoff + (size_t)r*64 + c4);
            *(uint4*)&ql[r*FQP + c4] = *(const uint4*)(ql2 + qoff + (size_t)r*64 + c4);
        }
        if (tid < 64) { m_s[tid] = -INFINITY; l_s[tid] = 0.f; }
    }

    float acc[8][4] = {};
    int iloc0 = warpM + g;

    for (int jt = 0; jt <= ti; jt++) {
        __syncthreads();                         // prior iteration fully consumed
        if (jt + 1 <= ti) issueKV(jt + 1);
        CP_COMMIT;
        if (tid < 128) {
            int n = (ti - jt)*64 - 63 + tid;
            bias_s[tid] = biasn[h*Sn + (n > 0 ? n : 0)];
        }
        asm volatile("cp.async.wait_group 1;" ::: "memory");  // stage jt ready
        __syncthreads();

        int st = jt & 1;
        const uint32_t* khb = khS + st*64*FQP;
        const uint32_t* klb = klS + st*64*FQP;
        const uint32_t* vhb = vhS + st*128*FVP;
        const uint32_t* vlb = vlS + st*128*FVP;

        // ---- S = Q K^T (3x bf16 compensated) ----
        float sacc[4][4] = {};
        #pragma unroll
        for (int ks = 0; ks < 8; ks++) {
            int c0 = 8*ks + t, c1 = c0 + 4;
            int rA = iloc0*FQP;
            uint32_t ah0 = qh[rA + c0],           ah1 = qh[rA + 8*FQP + c0];
            uint32_t ah2 = qh[rA + c1],           ah3 = qh[rA + 8*FQP + c1];
            uint32_t al0 = ql[rA + c0],           al1 = ql[rA + 8*FQP + c0];
            uint32_t al2 = ql[rA + c1],           al3 = ql[rA + 8*FQP + c1];
            #pragma unroll
            for (int nt = 0; nt < 4; nt++) {
                int rB = (warpNS + nt*8 + g)*FQP;
                uint32_t kb0 = khb[rB + c0], kb1 = khb[rB + c1];
                uint32_t kc0 = klb[rB + c0], kc1 = klb[rB + c1];
                MMA_BF16(sacc[nt], ah0, ah1, ah2, ah3, kb0, kb1);
                MMA_BF16(sacc[nt], ah0, ah1, ah2, ah3, kc0, kc1);
                MMA_BF16(sacc[nt], al0, al1, al2, al3, kb0, kb1);
            }
        }

        // ---- bias + causal mask ----
        int i0 = ti*64 + iloc0;
        #pragma unroll
        for (int nt = 0; nt < 4; nt++) {
            int jloc = warpNS + nt*8 + 2*t;
            int j0 = jt*64 + jloc;
            int d00 = iloc0 - jloc + 63;
            sacc[nt][0] = (j0     <= i0    ) ? (sacc[nt][0] + bias_s[d00    ]) * SCALE_ : -INFINITY;
            sacc[nt][1] = (j0 + 1 <= i0    ) ? (sacc[nt][1] + bias_s[d00 - 1]) * SCALE_ : -INFINITY;
            sacc[nt][2] = (j0     <= i0 + 8) ? (sacc[nt][2] + bias_s[d00 + 8]) * SCALE_ : -INFINITY;
            sacc[nt][3] = (j0 + 1 <= i0 + 8) ? (sacc[nt][3] + bias_s[d00 + 7]) * SCALE_ : -INFINITY;
        }

        // ---- row max ----
        float mx0 = fmaxf(fmaxf(sacc[0][0], sacc[0][1]), fmaxf(sacc[1][0], sacc[1][1]));
        mx0 = fmaxf(mx0, fmaxf(fmaxf(sacc[2][0], sacc[2][1]), fmaxf(sacc[3][0], sacc[3][1])));
        float mx1 = fmaxf(fmaxf(sacc[0][2], sacc[0][3]), fmaxf(sacc[1][2], sacc[1][3]));
        mx1 = fmaxf(mx1, fmaxf(fmaxf(sacc[2][2], sacc[2][3]), fmaxf(sacc[3][2], sacc[3][3])));
        mx0 = fmaxf(mx0, __shfl_xor_sync(0xffffffffu, mx0, 1));
        mx0 = fmaxf(mx0, __shfl_xor_sync(0xffffffffu, mx0, 2));
        mx1 = fmaxf(mx1, __shfl_xor_sync(0xffffffffu, mx1, 1));
        mx1 = fmaxf(mx1, __shfl_xor_sync(0xffffffffu, mx1, 2));
        if (t == 0) {
            rmax[grp*64 + iloc0]     = mx0;
            rmax[grp*64 + iloc0 + 8] = mx1;
        }
        __syncthreads();

        float mold0 = m_s[iloc0], mold1 = m_s[iloc0 + 8];
        float mnew0 = fmaxf(mold0, fmaxf(rmax[iloc0],     rmax[64 + iloc0]));
        float mnew1 = fmaxf(mold1, fmaxf(rmax[iloc0 + 8], rmax[64 + iloc0 + 8]));
        float fac0 = __expf(mold0 - mnew0);
        float fac1 = __expf(mold1 - mnew1);

        // ---- exp, P write (dedicated buffers), row sums ----
        float sum0 = 0.f, sum1 = 0.f;
        #pragma unroll
        for (int nt = 0; nt < 4; nt++) {
            float p00 = __expf(sacc[nt][0] - mnew0);
            float p01 = __expf(sacc[nt][1] - mnew0);
            float p10 = __expf(sacc[nt][2] - mnew1);
            float p11 = __expf(sacc[nt][3] - mnew1);
            sum0 += p00 + p01; sum1 += p10 + p11;
            int cc = (warpNS >> 1) + nt*4 + t;
            uint32_t hi, lo;
            cvt_pair(p00, p01, hi, lo);
            ph[iloc0*FPP + cc] = hi; pl[iloc0*FPP + cc] = lo;
            cvt_pair(p10, p11, hi, lo);
            ph[(iloc0+8)*FPP + cc] = hi; pl[(iloc0+8)*FPP + cc] = lo;
        }
        sum0 += __shfl_xor_sync(0xffffffffu, sum0, 1);
        sum0 += __shfl_xor_sync(0xffffffffu, sum0, 2);
        sum1 += __shfl_xor_sync(0xffffffffu, sum1, 1);
        sum1 += __shfl_xor_sync(0xffffffffu, sum1, 2);
        if (t == 0) {
            rsum[grp*64 + iloc0]     = sum0;
            rsum[grp*64 + iloc0 + 8] = sum1;
        }

        // ---- rescale O ----
        #pragma unroll
        for (int nt = 0; nt < 8; nt++) {
            acc[nt][0] *= fac0; acc[nt][1] *= fac0;
            acc[nt][2] *= fac1; acc[nt][3] *= fac1;
        }
        __syncthreads();

        if (tid < 64) {
            float mo = m_s[tid];
            float mn = fmaxf(mo, fmaxf(rmax[tid], rmax[64 + tid]));
            l_s[tid] = l_s[tid] * __expf(mo - mn) + rsum[tid] + rsum[64 + tid];
            m_s[tid] = mn;
        }

        // ---- O += P V (3x bf16 compensated) ----
        #pragma unroll
        for (int ks = 0; ks < 4; ks++) {
            int c0 = 8*ks + t, c1 = c0 + 4;
            int rA = iloc0*FPP;
            uint32_t ah0 = ph[rA + c0],           ah1 = ph[rA + 8*FPP + c0];
            uint32_t ah2 = ph[rA + c1],           ah3 = ph[rA + 8*FPP + c1];
            uint32_t al0 = pl[rA + c0],           al1 = pl[rA + 8*FPP + c0];
            uint32_t al2 = pl[rA + c1],           al3 = pl[rA + 8*FPP + c1];
            #pragma unroll
            for (int nt = 0; nt < 8; nt++) {
                int rB = (warpNV + nt*8 + g)*FVP;
                uint32_t vb0 = vhb[rB + c0], vb1 = vhb[rB + c1];
                uint32_t vc0 = vlb[rB + c0], vc1 = vlb[rB + c1];
                MMA_BF16(acc[nt], ah0, ah1, ah2, ah3, vb0, vb1);
                MMA_BF16(acc[nt], ah0, ah1, ah2, ah3, vc0, vc1);
                MMA_BF16(acc[nt], al0, al1, al2, al3, vb0, vb1);
            }
        }
    }

    __syncthreads();
    float inv0 = 1.f / l_s[iloc0];
    float inv1 = 1.f / l_s[iloc0 + 8];
    int i0 = ti*64 + iloc0;
    #pragma unroll
    for (int nt = 0; nt < 8; nt++) {
        int col = warpNV + nt*8 + 2*t;
        float* op0 = out + ((size_t)b*Sn + i0)*Dn + h*HDn + col;
        float* op1 = op0 + 8*(size_t)Dn;
        *(float2*)op0 = make_float2(tfv(acc[nt][0]*inv0), tfv(acc[nt][1]*inv0));
        *(float2*)op1 = make_float2(tfv(acc[nt][2]*inv1), tfv(acc[nt][3]*inv1));
    }
}

// ---------------- orchestration ----------------
extern "C" void kernel_launch(void* const* d_in, const int* in_sizes, int n_in,
                              void* d_out, int out_size) {
    (void)in_sizes; (void)n_in; (void)out_size;
    const int*   x     = (const int*)  d_in[0];
    const float* tok   = (const float*)d_in[1];
    const float* rel   = (const float*)d_in[2];
    const float* ln_g  = (const float*)d_in[3];
    const float* ln_b  = (const float*)d_in[4];
    const float* Wqkv  = (const float*)d_in[5];
    const float* bqkv  = (const float*)d_in[6];
    const float* Wo    = (const float*)d_in[7];
    const float* bo    = (const float*)d_in[8];
    const float* W1    = (const float*)d_in[9];
    const float* b1    = (const float*)d_in[10];
    const float* W2    = (const float*)d_in[11];
    const float* b2    = (const float*)d_in[12];
    const float* lnf_g = (const float*)d_in[13];
    const float* lnf_b = (const float*)d_in[14];
    const float* Whead = (const float*)d_in[15];
    const float* bhead = (const float*)d_in[16];
    float* out = (float*)d_out;

    float *h, *ln, *qkv, *ao, *mid, *biasn, *w;
    uint32_t *qh2, *ql2, *kh2, *kl2, *vh2T, *vl2T;
    cudaGetSymbolAddress((void**)&h,    g_h);
    cudaGetSymbolAddress((void**)&ln,   g_ln);
    cudaGetSymbolAddress((void**)&qkv,  g_qkv);
    cudaGetSymbolAddress((void**)&ao,   g_ao);
    cudaGetSymbolAddress((void**)&mid,  g_mid);
    cudaGetSymbolAddress((void**)&biasn,g_biasn);
    cudaGetSymbolAddress((void**)&w,    g_w);
    cudaGetSymbolAddress((void**)&qh2,  g_qh2);
    cudaGetSymbolAddress((void**)&ql2,  g_ql2);
    cudaGetSymbolAddress((void**)&kh2,  g_kh2);
    cudaGetSymbolAddress((void**)&kl2,  g_kl2);
    cudaGetSymbolAddress((void**)&vh2T, g_vh2T);
    cudaGetSymbolAddress((void**)&vl2T, g_vl2T);

    cudaFuncSetAttribute(flash_kernel, cudaFuncAttributeMaxDynamicSharedMemorySize,
                         FLASH_SMEM);
    cudaFuncSetAttribute(tgemm_kernel, cudaFuncAttributeMaxDynamicSharedMemorySize,
                         TG_SMEM);

    // pre-round all weights to tf32
    {
        struct { const float* s; float* d; size_t n; } cv[5] = {
            { Wqkv,  w + OFF_WQKV,  (size_t)Ln*3*Dn*Dn },
            { Wo,    w + OFF_WO,    (size_t)Ln*Dn*Dn   },
            { W1,    w + OFF_W1,    (size_t)Ln*Dn*FFn  },
            { W2,    w + OFF_W2,    (size_t)Ln*FFn*Dn  },
            { Whead, w + OFF_WHEAD, (size_t)Dn*Vn      },
        };
        for (int i = 0; i < 5; i++) {
            int n4 = (int)(cv[i].n >> 2);
            cvtw_kernel<<<(n4 + 255)/256, 256>>>((const float4*)cv[i].s,
                                                 (float4*)cv[i].d, n4);
        }
    }

    const float* v = qkv + (size_t)2*Mtok*Dn;

    embed_kernel<<<Mtok, 256>>>(x, tok, h);
    bias_init_kernel<<<Sn/256, 256>>>(rel, biasn);

    dim3 gDD(Dn/TBN,  Mtok/TBM);
    dim3 gQKV(Dn/TBN, Mtok/TBM, 3);
    dim3 gDF(FFn/TBN, Mtok/TBM);
    dim3 gDV(Mtok/TBM, Vn/TBN);           // M-fastest for the huge-N head GEMM

    for (int l = 0; l < Ln; l++) {
        ln_kernel<<<Mtok, 256>>>(h, ln_g + (size_t)(l*3+0)*Dn, ln_b + (size_t)(l*3+0)*Dn,
                                 nullptr, nullptr, ln, 0);
        // QKV: z=0/1 write packed Q/K directly (no float C); z=2 writes float V
        tgemm_kernel<<<gQKV, 256, TG_SMEM>>>(ln, w + OFF_WQKV + (size_t)l*3*Dn*Dn,
                                    bqkv + (size_t)l*3*Dn, nullptr, qkv,
                                    Mtok, Dn, Dn, 0, 0, 0,
                                    (size_t)Dn*Dn, (size_t)Dn, (size_t)Mtok*Dn,
                                    qh2, ql2, kh2, kl2);
        cvt_v_kernel<<<dim3(Sn/64, Bn*Hn), 256>>>(v, vh2T, vl2T);
        flash_kernel<<<dim3(Sn/64, Bn*Hn), 256, FLASH_SMEM>>>(
            qh2, ql2, kh2, kl2, vh2T, vl2T, biasn, ao);
        tgemm_kernel<<<gDD, 256, TG_SMEM>>>(ao, w + OFF_WO + (size_t)l*Dn*Dn,
                                   bo + (size_t)l*Dn, h, h,
                                   Mtok, Dn, Dn, 0, 0, 0, 0, 0, 0,
                                   nullptr, nullptr, nullptr, nullptr);
        ln_kernel<<<Mtok, 256>>>(h, ln_g + (size_t)(l*3+1)*Dn, ln_b + (size_t)(l*3+1)*Dn,
                                 ln_g + (size_t)(l*3+2)*Dn, ln_b + (size_t)(l*3+2)*Dn, ln, 1);
        tgemm_kernel<<<gDF, 256, TG_SMEM>>>(ln, w + OFF_W1 + (size_t)l*Dn*FFn,
                                   b1 + (size_t)l*FFn, nullptr, mid,
                                   Mtok, FFn, Dn, 1, 1, 0, 0, 0, 0,
                                   nullptr, nullptr, nullptr, nullptr);
        tgemm_kernel<<<gDD, 256, TG_SMEM>>>(mid, w + OFF_W2 + (size_t)l*FFn*Dn,
                                   b2 + (size_t)l*Dn, h, h,
                                   Mtok, Dn, FFn, 0, 0, 0, 0, 0, 0,
                                   nullptr, nullptr, nullptr, nullptr);
    }

    ln_kernel<<<Mtok, 256>>>(h, lnf_g, lnf_b, nullptr, nullptr, ln, 0);
    tgemm_kernel<<<gDV, 256, TG_SMEM>>>(ln, w + OFF_WHEAD, bhead, nullptr, out,
                               Mtok, Vn, Dn, 0, 0, 1, 0, 0, 0,
                               nullptr, nullptr, nullptr, nullptr);
}

// round 16
// speedup vs baseline: 1.0426x; 1.0036x over previous
#include <cuda_runtime.h>
#include <cuda_bf16.h>
#include <math.h>
#include <stdint.h>

// ---------------- problem constants ----------------
#define Bn   2
#define Sn   2048
#define Dn   1024
#define Hn   8
#define HDn  128
#define Vn   32000
#define Ln   6
#define Mtok (Bn*Sn)      // 4096
#define FFn  (4*Dn)       // 4096
#define SCALE_ 0.08838834764831845f   // 128^-0.5

// ---------------- scratch (device globals; no cudaMalloc allowed) ----------------
__device__ float g_h  [(size_t)Mtok*Dn];
__device__ float g_ln [(size_t)Mtok*Dn];
__device__ float g_qkv[(size_t)3*Mtok*Dn];
__device__ float g_ao [(size_t)Mtok*Dn];
__device__ float g_mid[(size_t)Mtok*FFn];
__device__ uint32_t g_qh2[(size_t)Bn*Hn*Sn*64];
__device__ uint32_t g_ql2[(size_t)Bn*Hn*Sn*64];
__device__ uint32_t g_kh2[(size_t)Bn*Hn*Sn*64];
__device__ uint32_t g_kl2[(size_t)Bn*Hn*Sn*64];
__device__ uint32_t g_vh2T[(size_t)Bn*Hn*HDn*(Sn/2)];
__device__ uint32_t g_vl2T[(size_t)Bn*Hn*HDn*(Sn/2)];
__device__ float g_biasn[Hn*Sn];
// tf32-pre-rounded weights ([K][N], same layout as inputs)
#define OFF_WQKV ((size_t)0)
#define OFF_WO   (OFF_WQKV + (size_t)Ln*3*Dn*Dn)
#define OFF_W1   (OFF_WO   + (size_t)Ln*Dn*Dn)
#define OFF_W2   (OFF_W1   + (size_t)Ln*Dn*FFn)
#define OFF_WHEAD (OFF_W2  + (size_t)Ln*FFn*Dn)
#define NW_TOTAL (OFF_WHEAD + (size_t)Dn*Vn)
__device__ float g_w[NW_TOTAL];

// segment bounds in float4 units (compile-time)
#define C0_ (OFF_WO    >> 2)
#define C1_ (OFF_W1    >> 2)
#define C2_ (OFF_W2    >> 2)
#define C3_ (OFF_WHEAD >> 2)
#define NW4 (NW_TOTAL  >> 2)
#define NW4H (NW4 >> 1)            // NW_TOTAL divisible by 8 (all segs multiples of 1M floats)

// ---------------- helpers ----------------
__device__ __forceinline__ uint32_t f2tf32(float f) {
    uint32_t u;
    asm("cvt.rna.tf32.f32 %0, %1;" : "=r"(u) : "f"(f));
    return u;
}
__device__ __forceinline__ float tfv(float f) { return __uint_as_float(f2tf32(f)); }

__device__ __forceinline__ void cp16(void* dst_smem, const void* src) {
    uint32_t d = (uint32_t)__cvta_generic_to_shared(dst_smem);
    asm volatile("cp.async.cg.shared.global [%0], [%1], 16;" :: "r"(d), "l"(src));
}
#define CP_COMMIT asm volatile("cp.async.commit_group;" ::: "memory")

// split f0,f1 into bf16 hi/lo pairs packed as b32 (low half = first element)
__device__ __forceinline__ void cvt_pair(float f0, float f1, uint32_t& hi, uint32_t& lo) {
    __nv_bfloat16 h0 = __float2bfloat16(f0);
    __nv_bfloat16 h1 = __float2bfloat16(f1);
    __nv_bfloat16 l0 = __float2bfloat16(f0 - __bfloat162float(h0));
    __nv_bfloat16 l1 = __float2bfloat16(f1 - __bfloat162float(h1));
    hi = ((uint32_t)__bfloat16_as_ushort(h1) << 16) | (uint32_t)__bfloat16_as_ushort(h0);
    lo = ((uint32_t)__bfloat16_as_ushort(l1) << 16) | (uint32_t)__bfloat16_as_ushort(l0);
}

#define MMA_BF16(C, A0,A1,A2,A3, B0,B1) \
    asm volatile("mma.sync.aligned.m16n8k16.row.col.f32.bf16.bf16.f32 " \
        "{%0,%1,%2,%3}, {%4,%5,%6,%7}, {%8,%9}, {%0,%1,%2,%3};" \
        : "+f"((C)[0]), "+f"((C)[1]), "+f"((C)[2]), "+f"((C)[3]) \
        : "r"(A0), "r"(A1), "r"(A2), "r"(A3), "r"(B0), "r"(B1))

#define MMA_TF32(C, A0,A1,A2,A3, B0,B1) \
    asm volatile("mma.sync.aligned.m16n8k8.row.col.f32.tf32.tf32.f32 " \
        "{%0,%1,%2,%3}, {%4,%5,%6,%7}, {%8,%9}, {%0,%1,%2,%3};" \
        : "+f"((C)[0]), "+f"((C)[1]), "+f"((C)[2]), "+f"((C)[3]) \
        : "r"(A0), "r"(A1), "r"(A2), "r"(A3), "r"(B0), "r"(B1))

__device__ __forceinline__ float blockReduceSum(float v, float* sm) {
    int lane = threadIdx.x & 31, wid = threadIdx.x >> 5;
    #pragma unroll
    for (int o = 16; o > 0; o >>= 1) v += __shfl_xor_sync(0xffffffffu, v, o);
    if (lane == 0) sm[wid] = v;
    __syncthreads();
    if (threadIdx.x < 32) {
        float t = (threadIdx.x < 8) ? sm[threadIdx.x] : 0.f;
        #pragma unroll
        for (int o = 4; o > 0; o >>= 1) t += __shfl_xor_sync(0xffffffffu, t, o);
        if (threadIdx.x == 0) sm[0] = t;
    }
    __syncthreads();
    float r = sm[0];
    __syncthreads();
    return r;
}

// ---------------- merged weight tf32 pre-round (all 5 tensors, 1 launch) ----------------
__global__ __launch_bounds__(256)
void cvtw_all_kernel(const float4* __restrict__ s0, const float4* __restrict__ s1,
                     const float4* __restrict__ s2, const float4* __restrict__ s3,
                     const float4* __restrict__ s4, float4* __restrict__ dst) {
    size_t i = (size_t)blockIdx.x * 256 + threadIdx.x;
    if (i >= NW4H) return;
    #pragma unroll
    for (int half = 0; half < 2; half++) {
        size_t j = i + (size_t)half * NW4H;
        const float4* src;
        size_t base;
        if      (j < C0_) { src = s0; base = 0;   }
        else if (j < C1_) { src = s1; base = C0_; }
        else if (j < C2_) { src = s2; base = C1_; }
        else if (j < C3_) { src = s3; base = C2_; }
        else              { src = s4; base = C3_; }
        float4 v = src[j - base];
        dst[j] = make_float4(tfv(v.x), tfv(v.y), tfv(v.z), tfv(v.w));
    }
}

// ---------------- embedding gather ----------------
__global__ void embed_kernel(const int* __restrict__ x,
                             const float* __restrict__ emb,
                             float* __restrict__ h) {
    int t = blockIdx.x;
    int tok = x[t];
    ((float4*)(h + (size_t)t*Dn))[threadIdx.x] =
        ((const float4*)(emb + (size_t)tok*Dn))[threadIdx.x];
}

// ---------------- LayerNorm (optionally fused double LN); output tf32-rounded ----------------
__global__ __launch_bounds__(256)
void ln_kernel(const float* __restrict__ x,
               const float* __restrict__ g,  const float* __restrict__ b,
               const float* __restrict__ g2, const float* __restrict__ b2,
               float* __restrict__ y, int dbl) {
    __shared__ float sm[32];
    int row = blockIdx.x;
    float4 v = ((const float4*)(x + (size_t)row*Dn))[threadIdx.x];
    float s  = v.x + v.y + v.z + v.w;
    float ss = v.x*v.x + v.y*v.y + v.z*v.z + v.w*v.w;
    float sum   = blockReduceSum(s, sm);
    float sumsq = blockReduceSum(ss, sm);
    float mean = sum * (1.f/Dn);
    float var  = sumsq * (1.f/Dn) - mean*mean;
    float r = rsqrtf(var + 1e-5f);
    int c = threadIdx.x * 4;
    float4 gv = *(const float4*)(g + c);
    float4 bv = *(const float4*)(b + c);
    float4 o;
    o.x = (v.x - mean)*r*gv.x + bv.x;
    o.y = (v.y - mean)*r*gv.y + bv.y;
    o.z = (v.z - mean)*r*gv.z + bv.z;
    o.w = (v.w - mean)*r*gv.w + bv.w;
    if (dbl) {
        s  = o.x + o.y + o.z + o.w;
        ss = o.x*o.x + o.y*o.y + o.z*o.z + o.w*o.w;
        sum   = blockReduceSum(s, sm);
        sumsq = blockReduceSum(ss, sm);
        mean = sum * (1.f/Dn);
        var  = sumsq * (1.f/Dn) - mean*mean;
        r = rsqrtf(var + 1e-5f);
        float4 g2v = *(const float4*)(g2 + c);
        float4 b2v = *(const float4*)(b2 + c);
        o.x = (o.x - mean)*r*g2v.x + b2v.x;
        o.y = (o.y - mean)*r*g2v.y + b2v.y;
        o.z = (o.z - mean)*r*g2v.z + b2v.z;
        o.w = (o.w - mean)*r*g2v.w + b2v.w;
    }
    o.x = tfv(o.x); o.y = tfv(o.y); o.z = tfv(o.z); o.w = tfv(o.w);
    ((float4*)(y + (size_t)row*Dn))[threadIdx.x] = o;
}

// ---------------- TF32 tensor-core GEMM, cp.async 4-stage pipeline (frozen) ----------------
// Inputs MUST be tf32-pre-rounded (mma truncation is then exact).
// If qh2 != null and blockIdx.z < 2: write ONLY packed bf16 hi/lo Q/K (no float C).
#define TBM 128
#define TBN 128
#define SA_PITCH 20
#define SB_PITCH 136
#define STG_A (128*SA_PITCH)
#define STG_B (16*SB_PITCH)
#define STG   (STG_A + STG_B)
#define TG_SMEM (4*STG*4)

__global__ __launch_bounds__(256, 2)
void tgemm_kernel(const float* __restrict__ A, const float* __restrict__ B,
                  const float* __restrict__ bias, const float* __restrict__ add,
                  float* __restrict__ C, int M, int N, int K,
                  int relu, int round_out, int swapxy,
                  size_t zB, size_t zBias, size_t zC,
                  uint32_t* __restrict__ qh2, uint32_t* __restrict__ ql2,
                  uint32_t* __restrict__ kh2, uint32_t* __restrict__ kl2) {
    extern __shared__ float smf[];

    B += (size_t)blockIdx.z * zB;
    if (bias) bias += (size_t)blockIdx.z * zBias;
    C += (size_t)blockIdx.z * zC;

    uint32_t* cvh = nullptr;
    uint32_t* cvl = nullptr;
    if (qh2) {
        if (blockIdx.z == 0)      { cvh = qh2; cvl = ql2; }
        else if (blockIdx.z == 1) { cvh = kh2; cvl = kl2; }
    }

    int tid  = threadIdx.x;
    int bxm = swapxy ? blockIdx.x : blockIdx.y;
    int bxn = swapxy ? blockIdx.y : blockIdx.x;
    int brow = bxm * TBM;
    int bcol = bxn * TBN;

    int warp = tid >> 5, lane = tid & 31;
    int gid = lane >> 2, tig = lane & 3;
    int warpM = (warp >> 2) * 64;
    int warpN = (warp & 3) * 32;

    const float* Ag = A + (size_t)brow * K;
    const float* Bg = B + bcol;

    int am0 = tid >> 1,          ak0 = (tid & 1) << 3;
    int bk0 = tid >> 5,          bn0 = (tid & 31) << 2;
    int bk1 = bk0 + 8;

    int nslab = K >> 4;
    auto issue = [&](int s) {
        float* As_ = smf + (s & 3) * STG;
        float* Bs_ = As_ + STG_A;
        int k0 = s << 4;
        const float* ag = Ag + (size_t)am0*K + k0 + ak0;
        cp16(As_ + am0*SA_PITCH + ak0,     ag);
        cp16(As_ + am0*SA_PITCH + ak0 + 4, ag + 4);
        cp16(Bs_ + bk0*SB_PITCH + bn0, Bg + (size_t)(k0+bk0)*N + bn0);
        cp16(Bs_ + bk1*SB_PITCH + bn0, Bg + (size_t)(k0+bk1)*N + bn0);
    };

    issue(0); CP_COMMIT;
    issue(1); CP_COMMIT;
    issue(2); CP_COMMIT;

    float acc[4][4][4] = {};

    for (int i = 0; i < nslab; i++) {
        asm volatile("cp.async.wait_group 2;" ::: "memory");
        __syncthreads();
        const float* As_ = smf + (i & 3) * STG;
        const float* Bs_ = As_ + STG_A;
        #pragma unroll
        for (int ks = 0; ks < 2; ks++) {
            int kb = ks * 8;
            uint32_t af[4][4], bf[4][2];
            #pragma unroll
            for (int mt = 0; mt < 4; mt++) {
                int r = warpM + mt*16 + gid;
                af[mt][0] = __float_as_uint(As_[(size_t)r    *SA_PITCH + kb + tig    ]);
                af[mt][1] = __float_as_uint(As_[(size_t)(r+8)*SA_PITCH + kb + tig    ]);
                af[mt][2] = __float_as_uint(As_[(size_t)r    *SA_PITCH + kb + tig + 4]);
                af[mt][3] = __float_as_uint(As_[(size_t)(r+8)*SA_PITCH + kb + tig + 4]);
            }
            #pragma unroll
            for (int nt = 0; nt < 4; nt++) {
                int c = warpN + nt*8 + gid;
                bf[nt][0] = __float_as_uint(Bs_[(size_t)(kb+tig  )*SB_PITCH + c]);
                bf[nt][1] = __float_as_uint(Bs_[(size_t)(kb+tig+4)*SB_PITCH + c]);
            }
            #pragma unroll
            for (int mt = 0; mt < 4; mt++)
                #pragma unroll
                for (int nt = 0; nt < 4; nt++)
                    MMA_TF32(acc[mt][nt], af[mt][0], af[mt][1], af[mt][2], af[mt][3],
                             bf[nt][0], bf[nt][1]);
        }
        if (i + 3 < nslab) issue(i + 3);
        CP_COMMIT;
    }

    #pragma unroll
    for (int mt = 0; mt < 4; mt++) {
        int r0 = brow + warpM + mt*16 + gid;
        int r1 = r0 + 8;
        #pragma unroll
        for (int nt = 0; nt < 4; nt++) {
            int c = bcol + warpN + nt*8 + tig*2;
            float v00 = acc[mt][nt][0], v01 = acc[mt][nt][1];
            float v10 = acc[mt][nt][2], v11 = acc[mt][nt][3];
            if (bias) {
                float bb0 = bias[c], bb1 = bias[c+1];
                v00 += bb0; v01 += bb1; v10 += bb0; v11 += bb1;
            }
            if (relu) {
                v00 = fmaxf(v00, 0.f); v01 = fmaxf(v01, 0.f);
                v10 = fmaxf(v10, 0.f); v11 = fmaxf(v11, 0.f);
            }
            if (round_out) {
                v00 = tfv(v00); v01 = tfv(v01);
                v10 = tfv(v10); v11 = tfv(v11);
            }
            if (add) {
                const float* ad0 = add + (size_t)r0*N + c;
                const float* ad1 = add + (size_t)r1*N + c;
                v00 += ad0[0]; v01 += ad0[1];
                v10 += ad1[0]; v11 += ad1[1];
            }
            if (cvh) {
                int hh = c >> 7, hdp = (c & 127) >> 1;
                int bb0_ = r0 >> 11, ss0 = r0 & 2047;
                int bb1_ = r1 >> 11, ss1 = r1 & 2047;
                size_t o0 = ((size_t)(bb0_*Hn + hh)*Sn + ss0)*64 + hdp;
                size_t o1 = ((size_t)(bb1_*Hn + hh)*Sn + ss1)*64 + hdp;
                uint32_t hi, lo;
                cvt_pair(v00, v01, hi, lo);
                cvh[o0] = hi; cvl[o0] = lo;
                cvt_pair(v10, v11, hi, lo);
                cvh[o1] = hi; cvl[o1] = lo;
            } else {
                *(float2*)(C + (size_t)r0*N + c) = make_float2(v00, v01);
                *(float2*)(C + (size_t)r1*N + c) = make_float2(v10, v11);
            }
        }
    }
}

// ---------------- rel-pos bias table (layer-invariant) ----------------
__global__ void bias_init_kernel(const float* __restrict__ rel,
                                 float* __restrict__ biasn) {
    int n = blockIdx.x * 256 + threadIdx.x;
    if (n >= Sn) return;
    float inv_log8 = 1.0f / logf(8.0f);
    int bucket;
    if (n < 16) bucket = n;
    else {
        int vb = 16 + (int)((logf((float)n * (1.0f/16.0f)) * inv_log8) * 16.0f);
        bucket = vb < 31 ? vb : 31;
    }
    for (int h = 0; h < Hn; h++)
        biasn[h*Sn + n] = rel[bucket*Hn + h] * SCALE_;
}

// ---------------- convert V transposed: [bh][hd][kv pairs] ----------------
__global__ __launch_bounds__(256)
void cvt_v_kernel(const float* __restrict__ v,
                  uint32_t* __restrict__ vh2T, uint32_t* __restrict__ vl2T) {
    __shared__ float vs[64][129];
    int kv0 = blockIdx.x * 64;
    int bh = blockIdx.y, b = bh >> 3, h = bh & 7;
    const float* vb = v + ((size_t)b*Sn + kv0)*Dn + h*HDn;
    for (int idx = threadIdx.x; idx < 64*32; idx += 256) {
        int r = idx >> 5, c4 = (idx & 31) << 2;
        float4 t = *(const float4*)(vb + (size_t)r*Dn + c4);
        vs[r][c4] = t.x; vs[r][c4+1] = t.y; vs[r][c4+2] = t.z; vs[r][c4+3] = t.w;
    }
    __syncthreads();
    int hd  = threadIdx.x >> 1;
    int kp0 = (threadIdx.x & 1) * 16;
    uint32_t* oh = vh2T + ((size_t)bh*HDn + hd)*(Sn/2) + (kv0 >> 1) + kp0;
    uint32_t* ol = vl2T + ((size_t)bh*HDn + hd)*(Sn/2) + (kv0 >> 1) + kp0;
    for (int kp = 0; kp < 16; kp++) {
        float f0 = vs[2*(kp0+kp)  ][hd];
        float f1 = vs[2*(kp0+kp)+1][hd];
        uint32_t hi, lo;
        cvt_pair(f0, f1, hi, lo);
        oh[kp] = hi; ol[kp] = lo;
    }
}

// ---------------- fused flash attention (cp.async double-buffered K/V) ----------------
#define FQP 68
#define FVP 36
#define FPP 36
#define FSM_U32 (2*64*FQP + 4*64*FQP + 4*128*FVP + 2*64*FPP)
#define FLASH_SMEM ((FSM_U32 + 512) * 4)   // 198,656 bytes

__global__ __launch_bounds__(256)
void flash_kernel(const uint32_t* __restrict__ qh2, const uint32_t* __restrict__ ql2,
                  const uint32_t* __restrict__ kh2, const uint32_t* __restrict__ kl2,
                  const uint32_t* __restrict__ vh2T, const uint32_t* __restrict__ vl2T,
                  const float* __restrict__ biasn, float* __restrict__ out) {
    extern __shared__ uint32_t smu[];
    uint32_t* qh  = smu;
    uint32_t* ql  = smu + 64*FQP;
    uint32_t* khS = smu + 2*64*FQP;          // 2 stages of 64*FQP
    uint32_t* klS = khS + 2*64*FQP;
    uint32_t* vhS = klS + 2*64*FQP;          // 2 stages of 128*FVP
    uint32_t* vlS = vhS + 2*128*FVP;
    uint32_t* ph  = vlS + 2*128*FVP;         // P hi (64*FPP)
    uint32_t* pl  = ph + 64*FPP;
    float* m_s    = (float*)(pl + 64*FPP);
    float* l_s    = m_s + 64;
    float* rmax   = l_s + 64;
    float* rsum   = rmax + 128;
    float* bias_s = rsum + 128;

    int ti = gridDim.x - 1 - (int)blockIdx.x;
    int bh = blockIdx.y, b = bh >> 3, h = bh & 7;
    int tid = threadIdx.x;
    int warp = tid >> 5, lane = tid & 31;
    int g = lane >> 2, t = lane & 3;
    int warpM  = (warp & 3) << 4;
    int grp    = warp >> 2;
    int warpNS = grp << 5;
    int warpNV = grp << 6;

    auto issueKV = [&](int jt) {
        int st = jt & 1;
        uint32_t* kh_ = khS + st*64*FQP;
        uint32_t* kl_ = klS + st*64*FQP;
        uint32_t* vh_ = vhS + st*128*FVP;
        uint32_t* vl_ = vlS + st*128*FVP;
        size_t koff = ((size_t)bh*Sn + (size_t)jt*64)*64;
        #pragma unroll
        for (int i = 0; i < 4; i++) {           // K: 64 rows x 16 chunks = 1024 chunks
            int c = tid + (i << 8);
            int r = c >> 4, o4 = (c & 15) << 2;
            cp16(kh_ + r*FQP + o4, kh2 + koff + (size_t)r*64 + o4);
            cp16(kl_ + r*FQP + o4, kl2 + koff + (size_t)r*64 + o4);
        }
        size_t voff = (size_t)bh*HDn*(Sn/2) + (size_t)jt*32;
        #pragma unroll
        for (int i = 0; i < 4; i++) {           // V: 128 rows x 8 chunks = 1024 chunks
            int c = tid + (i << 8);
            int r = c >> 3, o4 = (c & 7) << 2;
            cp16(vh_ + r*FVP + o4, vh2T + voff + (size_t)r*(Sn/2) + o4);
            cp16(vl_ + r*FVP + o4, vl2T + voff + (size_t)r*(Sn/2) + o4);
        }
    };

    // prologue: start K/V(0), stage Q, init stats
    issueKV(0); CP_COMMIT;
    {
        size_t qoff = ((size_t)bh*Sn + (size_t)ti*64)*64;
        for (int idx = tid; idx < 1024; idx += 256) {
            int r = idx >> 4, c4 = (idx & 15) << 2;
            *(uint4*)&qh[r*FQP + c4] = *(const uint4*)(qh2 + qoff + (size_t)r*64 + c4);
            *(uint4*)&ql[r*FQP + c4] = *(const uint4*)(ql2 + qoff + (size_t)r*64 + c4);
        }
        if (tid < 64) { m_s[tid] = -INFINITY; l_s[tid] = 0.f; }
    }

    float acc[8][4] = {};
    int iloc0 = warpM + g;

    for (int jt = 0; jt <= ti; jt++) {
        __syncthreads();                         // prior iteration fully consumed
        if (jt + 1 <= ti) issueKV(jt + 1);
        CP_COMMIT;
        if (tid < 128) {
            int n = (ti - jt)*64 - 63 + tid;
            bias_s[tid] = biasn[h*Sn + (n > 0 ? n : 0)];
        }
        asm volatile("cp.async.wait_group 1;" ::: "memory");  // stage jt ready
        __syncthreads();

        int st = jt & 1;
        const uint32_t* khb = khS + st*64*FQP;
        const uint32_t* klb = klS + st*64*FQP;
        const uint32_t* vhb = vhS + st*128*FVP;
        const uint32_t* vlb = vlS + st*128*FVP;

        // ---- S = Q K^T (3x bf16 compensated) ----
        float sacc[4][4] = {};
        #pragma unroll
        for (int ks = 0; ks < 8; ks++) {
            int c0 = 8*ks + t, c1 = c0 + 4;
            int rA = iloc0*FQP;
            uint32_t ah0 = qh[rA + c0],           ah1 = qh[rA + 8*FQP + c0];
            uint32_t ah2 = qh[rA + c1],           ah3 = qh[rA + 8*FQP + c1];
            uint32_t al0 = ql[rA + c0],           al1 = ql[rA + 8*FQP + c0];
            uint32_t al2 = ql[rA + c1],           al3 = ql[rA + 8*FQP + c1];
            #pragma unroll
            for (int nt = 0; nt < 4; nt++) {
                int rB = (warpNS + nt*8 + g)*FQP;
                uint32_t kb0 = khb[rB + c0], kb1 = khb[rB + c1];
                uint32_t kc0 = klb[rB + c0], kc1 = klb[rB + c1];
                MMA_BF16(sacc[nt], ah0, ah1, ah2, ah3, kb0, kb1);
                MMA_BF16(sacc[nt], ah0, ah1, ah2, ah3, kc0, kc1);
                MMA_BF16(sacc[nt], al0, al1, al2, al3, kb0, kb1);
            }
        }

        // ---- bias + causal mask ----
        int i0 = ti*64 + iloc0;
        #pragma unroll
        for (int nt = 0; nt < 4; nt++) {
            int jloc = warpNS + nt*8 + 2*t;
            int j0 = jt*64 + jloc;
            int d00 = iloc0 - jloc + 63;
            sacc[nt][0] = (j0     <= i0    ) ? (sacc[nt][0] + bias_s[d00    ]) * SCALE_ : -INFINITY;
            sacc[nt][1] = (j0 + 1 <= i0    ) ? (sacc[nt][1] + bias_s[d00 - 1]) * SCALE_ : -INFINITY;
            sacc[nt][2] = (j0     <= i0 + 8) ? (sacc[nt][2] + bias_s[d00 + 8]) * SCALE_ : -INFINITY;
            sacc[nt][3] = (j0 + 1 <= i0 + 8) ? (sacc[nt][3] + bias_s[d00 + 7]) * SCALE_ : -INFINITY;
        }

        // ---- row max ----
        float mx0 = fmaxf(fmaxf(sacc[0][0], sacc[0][1]), fmaxf(sacc[1][0], sacc[1][1]));
        mx0 = fmaxf(mx0, fmaxf(fmaxf(sacc[2][0], sacc[2][1]), fmaxf(sacc[3][0], sacc[3][1])));
        float mx1 = fmaxf(fmaxf(sacc[0][2], sacc[0][3]), fmaxf(sacc[1][2], sacc[1][3]));
        mx1 = fmaxf(mx1, fmaxf(fmaxf(sacc[2][2], sacc[2][3]), fmaxf(sacc[3][2], sacc[3][3])));
        mx0 = fmaxf(mx0, __shfl_xor_sync(0xffffffffu, mx0, 1));
        mx0 = fmaxf(mx0, __shfl_xor_sync(0xffffffffu, mx0, 2));
        mx1 = fmaxf(mx1, __shfl_xor_sync(0xffffffffu, mx1, 1));
        mx1 = fmaxf(mx1, __shfl_xor_sync(0xffffffffu, mx1, 2));
        if (t == 0) {
            rmax[grp*64 + iloc0]     = mx0;
            rmax[grp*64 + iloc0 + 8] = mx1;
        }
        __syncthreads();

        float mold0 = m_s[iloc0], mold1 = m_s[iloc0 + 8];
        float mnew0 = fmaxf(mold0, fmaxf(rmax[iloc0],     rmax[64 + iloc0]));
        float mnew1 = fmaxf(mold1, fmaxf(rmax[iloc0 + 8], rmax[64 + iloc0 + 8]));
        float fac0 = __expf(mold0 - mnew0);
        float fac1 = __expf(mold1 - mnew1);

        // ---- exp, P write (dedicated buffers), row sums ----
        float sum0 = 0.f, sum1 = 0.f;
        #pragma unroll
        for (int nt = 0; nt < 4; nt++) {
            float p00 = __expf(sacc[nt][0] - mnew0);
            float p01 = __expf(sacc[nt][1] - mnew0);
            float p10 = __expf(sacc[nt][2] - mnew1);
            float p11 = __expf(sacc[nt][3] - mnew1);
            sum0 += p00 + p01; sum1 += p10 + p11;
            int cc = (warpNS >> 1) + nt*4 + t;
            uint32_t hi, lo;
            cvt_pair(p00, p01, hi, lo);
            ph[iloc0*FPP + cc] = hi; pl[iloc0*FPP + cc] = lo;
            cvt_pair(p10, p11, hi, lo);
            ph[(iloc0+8)*FPP + cc] = hi; pl[(iloc0+8)*FPP + cc] = lo;
        }
        sum0 += __shfl_xor_sync(0xffffffffu, sum0, 1);
        sum0 += __shfl_xor_sync(0xffffffffu, sum0, 2);
        sum1 += __shfl_xor_sync(0xffffffffu, sum1, 1);
        sum1 += __shfl_xor_sync(0xffffffffu, sum1, 2);
        if (t == 0) {
            rsum[grp*64 + iloc0]     = sum0;
            rsum[grp*64 + iloc0 + 8] = sum1;
        }

        // ---- rescale O ----
        #pragma unroll
        for (int nt = 0; nt < 8; nt++) {
            acc[nt][0] *= fac0; acc[nt][1] *= fac0;
            acc[nt][2] *= fac1; acc[nt][3] *= fac1;
        }
        __syncthreads();

        if (tid < 64) {
            float mo = m_s[tid];
            float mn = fmaxf(mo, fmaxf(rmax[tid], rmax[64 + tid]));
            l_s[tid] = l_s[tid] * __expf(mo - mn) + rsum[tid] + rsum[64 + tid];
            m_s[tid] = mn;
        }

        // ---- O += P V (3x bf16 compensated) ----
        #pragma unroll
        for (int ks = 0; ks < 4; ks++) {
            int c0 = 8*ks + t, c1 = c0 + 4;
            int rA = iloc0*FPP;
            uint32_t ah0 = ph[rA + c0],           ah1 = ph[rA + 8*FPP + c0];
            uint32_t ah2 = ph[rA + c1],           ah3 = ph[rA + 8*FPP + c1];
            uint32_t al0 = pl[rA + c0],           al1 = pl[rA + 8*FPP + c0];
            uint32_t al2 = pl[rA + c1],           al3 = pl[rA + 8*FPP + c1];
            #pragma unroll
            for (int nt = 0; nt < 8; nt++) {
                int rB = (warpNV + nt*8 + g)*FVP;
                uint32_t vb0 = vhb[rB + c0], vb1 = vhb[rB + c1];
                uint32_t vc0 = vlb[rB + c0], vc1 = vlb[rB + c1];
                MMA_BF16(acc[nt], ah0, ah1, ah2, ah3, vb0, vb1);
                MMA_BF16(acc[nt], ah0, ah1, ah2, ah3, vc0, vc1);
                MMA_BF16(acc[nt], al0, al1, al2, al3, vb0, vb1);
            }
        }
    }

    __syncthreads();
    float inv0 = 1.f / l_s[iloc0];
    float inv1 = 1.f / l_s[iloc0 + 8];
    int i0 = ti*64 + iloc0;
    #pragma unroll
    for (int nt = 0; nt < 8; nt++) {
        int col = warpNV + nt*8 + 2*t;
        float* op0 = out + ((size_t)b*Sn + i0)*Dn + h*HDn + col;
        float* op1 = op0 + 8*(size_t)Dn;
        *(float2*)op0 = make_float2(tfv(acc[nt][0]*inv0), tfv(acc[nt][1]*inv0));
        *(float2*)op1 = make_float2(tfv(acc[nt][2]*inv1), tfv(acc[nt][3]*inv1));
    }
}

// ---------------- orchestration ----------------
extern "C" void kernel_launch(void* const* d_in, const int* in_sizes, int n_in,
                              void* d_out, int out_size) {
    (void)in_sizes; (void)n_in; (void)out_size;
    const int*   x     = (const int*)  d_in[0];
    const float* tok   = (const float*)d_in[1];
    const float* rel   = (const float*)d_in[2];
    const float* ln_g  = (const float*)d_in[3];
    const float* ln_b  = (const float*)d_in[4];
    const float* Wqkv  = (const float*)d_in[5];
    const float* bqkv  = (const float*)d_in[6];
    const float* Wo    = (const float*)d_in[7];
    const float* bo    = (const float*)d_in[8];
    const float* W1    = (const float*)d_in[9];
    const float* b1    = (const float*)d_in[10];
    const float* W2    = (const float*)d_in[11];
    const float* b2    = (const float*)d_in[12];
    const float* lnf_g = (const float*)d_in[13];
    const float* lnf_b = (const float*)d_in[14];
    const float* Whead = (const float*)d_in[15];
    const float* bhead = (const float*)d_in[16];
    float* out = (float*)d_out;

    float *h, *ln, *qkv, *ao, *mid, *biasn, *w;
    uint32_t *qh2, *ql2, *kh2, *kl2, *vh2T, *vl2T;
    cudaGetSymbolAddress((void**)&h,    g_h);
    cudaGetSymbolAddress((void**)&ln,   g_ln);
    cudaGetSymbolAddress((void**)&qkv,  g_qkv);
    cudaGetSymbolAddress((void**)&ao,   g_ao);
    cudaGetSymbolAddress((void**)&mid,  g_mid);
    cudaGetSymbolAddress((void**)&biasn,g_biasn);
    cudaGetSymbolAddress((void**)&w,    g_w);
    cudaGetSymbolAddress((void**)&qh2,  g_qh2);
    cudaGetSymbolAddress((void**)&ql2,  g_ql2);
    cudaGetSymbolAddress((void**)&kh2,  g_kh2);
    cudaGetSymbolAddress((void**)&kl2,  g_kl2);
    cudaGetSymbolAddress((void**)&vh2T, g_vh2T);
    cudaGetSymbolAddress((void**)&vl2T, g_vl2T);

    cudaFuncSetAttribute(flash_kernel, cudaFuncAttributeMaxDynamicSharedMemorySize,
                         FLASH_SMEM);
    cudaFuncSetAttribute(tgemm_kernel, cudaFuncAttributeMaxDynamicSharedMemorySize,
                         TG_SMEM);

    // pre-round all weights to tf32 (single merged launch, 2 float4/thread)
    {
        int nblk = (int)((NW4H + 255) / 256);
        cvtw_all_kernel<<<nblk, 256>>>((const float4*)Wqkv, (const float4*)Wo,
                                       (const float4*)W1,   (const float4*)W2,
                                       (const float4*)Whead, (float4*)w);
    }

    const float* v = qkv + (size_t)2*Mtok*Dn;

    embed_kernel<<<Mtok, 256>>>(x, tok, h);
    bias_init_kernel<<<Sn/256, 256>>>(rel, biasn);

    dim3 gDD(Dn/TBN,  Mtok/TBM);
    dim3 gQKV(Dn/TBN, Mtok/TBM, 3);
    dim3 gDF(FFn/TBN, Mtok/TBM);
    dim3 gDV(Mtok/TBM, Vn/TBN);           // M-fastest for the huge-N head GEMM

    for (int l = 0; l < Ln; l++) {
        ln_kernel<<<Mtok, 256>>>(h, ln_g + (size_t)(l*3+0)*Dn, ln_b + (size_t)(l*3+0)*Dn,
                                 nullptr, nullptr, ln, 0);
        // QKV: z=0/1 write packed Q/K directly (no float C); z=2 writes float V
        tgemm_kernel<<<gQKV, 256, TG_SMEM>>>(ln, w + OFF_WQKV + (size_t)l*3*Dn*Dn,
                                    bqkv + (size_t)l*3*Dn, nullptr, qkv,
                                    Mtok, Dn, Dn, 0, 0, 0,
                                    (size_t)Dn*Dn, (size_t)Dn, (size_t)Mtok*Dn,
                                    qh2, ql2, kh2, kl2);
        cvt_v_kernel<<<dim3(Sn/64, Bn*Hn), 256>>>(v, vh2T, vl2T);
        flash_kernel<<<dim3(Sn/64, Bn*Hn), 256, FLASH_SMEM>>>(
            qh2, ql2, kh2, kl2, vh2T, vl2T, biasn, ao);
        tgemm_kernel<<<gDD, 256, TG_SMEM>>>(ao, w + OFF_WO + (size_t)l*Dn*Dn,
                                   bo + (size_t)l*Dn, h, h,
                                   Mtok, Dn, Dn, 0, 0, 0, 0, 0, 0,
                                   nullptr, nullptr, nullptr, nullptr);
        ln_kernel<<<Mtok, 256>>>(h, ln_g + (size_t)(l*3+1)*Dn, ln_b + (size_t)(l*3+1)*Dn,
                                 ln_g + (size_t)(l*3+2)*Dn, ln_b + (size_t)(l*3+2)*Dn, ln, 1);
        tgemm_kernel<<<gDF, 256, TG_SMEM>>>(ln, w + OFF_W1 + (size_t)l*Dn*FFn,
                                   b1 + (size_t)l*FFn, nullptr, mid,
                                   Mtok, FFn, Dn, 1, 1, 0, 0, 0, 0,
                                   nullptr, nullptr, nullptr, nullptr);
        tgemm_kernel<<<gDD, 256, TG_SMEM>>>(mid, w + OFF_W2 + (size_t)l*FFn*Dn,
                                   b2 + (size_t)l*Dn, h, h,
                                   Mtok, Dn, FFn, 0, 0, 0, 0, 0, 0,
                                   nullptr, nullptr, nullptr, nullptr);
    }

    ln_kernel<<<Mtok, 256>>>(h, lnf_g, lnf_b, nullptr, nullptr, ln, 0);
    tgemm_kernel<<<gDV, 256, TG_SMEM>>>(ln, w + OFF_WHEAD, bhead, nullptr, out,
                               Mtok, Vn, Dn, 0, 0, 1, 0, 0, 0,
                               nullptr, nullptr, nullptr, nullptr);
}